// round 1
// baseline (speedup 1.0000x reference)
#include <cuda_runtime.h>

// Problem constants
constexpr int Bc  = 2;
constexpr int Sc  = 2048;
constexpr int Dc  = 1024;
constexpr int Hc  = 16;
constexpr int HDc = 64;
constexpr int Mc  = Bc * Sc;   // 4096 rows for the projection GEMMs

// Scratch (allocation-free rule: __device__ globals). 4 x 16MB = 64MB.
__device__ float g_Q[Bc * Hc * Sc * HDc];
__device__ float g_K[Bc * Hc * Sc * HDc];
__device__ float g_V[Bc * Hc * Sc * HDc];
__device__ float g_ctx[Mc * Dc];

// ---------------------------------------------------------------------------
// GEMM: out[m][n] = sum_k A[m][k] * W[n][k] + bias[n]
// M=4096, N=1024, K=1024. Tiles 128x128x16, 256 threads, 8x8 micro-tile.
// PERMUTE=true stores head-major: out[((b*H+h)*S + s)*HD + hd]
// ---------------------------------------------------------------------------
template <bool PERMUTE>
__global__ __launch_bounds__(256) void gemm_bias_kernel(
    const float* __restrict__ A, const float* __restrict__ W,
    const float* __restrict__ bias, float* __restrict__ out)
{
    constexpr int K = 1024;
    __shared__ float sA[16][128];
    __shared__ float sB[16][128];

    const int tid = threadIdx.x;
    const int tx  = tid & 15;        // 0..15  (N direction)
    const int ty  = tid >> 4;        // 0..15  (M direction)
    const int bm  = blockIdx.y << 7;
    const int bn  = blockIdx.x << 7;

    float acc[8][8];
#pragma unroll
    for (int i = 0; i < 8; ++i)
#pragma unroll
        for (int j = 0; j < 8; ++j) acc[i][j] = 0.f;

    for (int k0 = 0; k0 < K; k0 += 16) {
        // cooperative load: 128x16 of A and of W (transposed into smem)
#pragma unroll
        for (int it = 0; it < 2; ++it) {
            int i   = tid + it * 256;          // 0..511
            int row = i >> 2;                  // 0..127
            int kc  = (i & 3) << 2;            // 0,4,8,12
            float4 va = *(const float4*)&A[(size_t)(bm + row) * K + k0 + kc];
            sA[kc + 0][row] = va.x; sA[kc + 1][row] = va.y;
            sA[kc + 2][row] = va.z; sA[kc + 3][row] = va.w;
            float4 vb = *(const float4*)&W[(size_t)(bn + row) * K + k0 + kc];
            sB[kc + 0][row] = vb.x; sB[kc + 1][row] = vb.y;
            sB[kc + 2][row] = vb.z; sB[kc + 3][row] = vb.w;
        }
        __syncthreads();

#pragma unroll
        for (int k = 0; k < 16; ++k) {
            float a[8], b[8];
            *(float4*)&a[0] = *(const float4*)&sA[k][ty * 4];
            *(float4*)&a[4] = *(const float4*)&sA[k][64 + ty * 4];
            *(float4*)&b[0] = *(const float4*)&sB[k][tx * 4];
            *(float4*)&b[4] = *(const float4*)&sB[k][64 + tx * 4];
#pragma unroll
            for (int i = 0; i < 8; ++i)
#pragma unroll
                for (int j = 0; j < 8; ++j) acc[i][j] += a[i] * b[j];
        }
        __syncthreads();
    }

    // store with bias
#pragma unroll
    for (int i = 0; i < 8; ++i) {
        int rlocal = (i < 4) ? (ty * 4 + i) : (64 + ty * 4 + (i - 4));
        int row    = bm + rlocal;
#pragma unroll
        for (int j = 0; j < 8; ++j) {
            int clocal = (j < 4) ? (tx * 4 + j) : (64 + tx * 4 + (j - 4));
            int col    = bn + clocal;
            float v = acc[i][j] + bias[col];
            if (PERMUTE) {
                int b_ = row >> 11;           // row / S
                int s  = row & 2047;          // row % S
                int h  = col >> 6;            // col / HD
                int hd = col & 63;            // col % HD
                out[(((size_t)(b_ * Hc + h) * Sc + s) << 6) + hd] = v;
            } else {
                out[(size_t)row * Dc + col] = v;
            }
        }
    }
}

// ---------------------------------------------------------------------------
// Flash attention (causal), fp32.
// One block handles a 64-row query tile of one (b,h). 256 threads.
// Thread t: row r = t>>2 (0..63), quad q = t&3.
//   scores: owns cols c = q + 4*i (i=0..15)    -> conflict-free sK reads
//   ctx:    owns dims d = q*16 + j (j=0..15)   -> <=2-way sV reads
// Dynamic smem: sQ 64x64 | sK 64x68 (reused for P) | sV 64x68  = 51200 B
// ---------------------------------------------------------------------------
constexpr int ATTN_SMEM_FLOATS = 64 * 64 + 64 * 68 + 64 * 68;   // 12800
constexpr int ATTN_SMEM_BYTES  = ATTN_SMEM_FLOATS * 4;          // 51200

__global__ __launch_bounds__(256) void attn_kernel(
    const float* __restrict__ Q, const float* __restrict__ Kt,
    const float* __restrict__ V, float* __restrict__ ctx)
{
    extern __shared__ float smem[];
    float* sQ = smem;                 // stride 64
    float* sK = smem + 64 * 64;       // stride 68 (also holds P)
    float* sV = sK + 64 * 68;         // stride 68

    const int tid = threadIdx.x;
    const int r   = tid >> 2;         // query row in tile
    const int q   = tid & 3;          // quad id
    const int qt  = blockIdx.x;       // query tile (0..31)
    const int bh  = blockIdx.y;       // b*H + h

    const float scale = 0.125f;       // 1/sqrt(64)

    // load Q tile (scaled)
    const float* Qb = Q + ((size_t)bh * Sc + qt * 64) * HDc;
#pragma unroll
    for (int it = 0; it < 4; ++it) {
        int i  = tid + it * 256;      // 0..1023
        int rr = i >> 4;
        int d4 = (i & 15) << 2;
        float4 v = *(const float4*)&Qb[rr * 64 + d4];
        v.x *= scale; v.y *= scale; v.z *= scale; v.w *= scale;
        *(float4*)&sQ[rr * 64 + d4] = v;
    }

    float m = -1e30f, l = 0.f;
    float ctxa[16];
#pragma unroll
    for (int j = 0; j < 16; ++j) ctxa[j] = 0.f;

    for (int kt = 0; kt <= qt; ++kt) {
        const float* Kb = Kt + ((size_t)bh * Sc + kt * 64) * HDc;
        const float* Vb = V  + ((size_t)bh * Sc + kt * 64) * HDc;

        __syncthreads();   // previous iter done with sK(P)/sV; sQ ready (iter 0)
#pragma unroll
        for (int it = 0; it < 4; ++it) {
            int i  = tid + it * 256;
            int rr = i >> 4;
            int d4 = (i & 15) << 2;
            *(float4*)&sK[rr * 68 + d4] = *(const float4*)&Kb[rr * 64 + d4];
            *(float4*)&sV[rr * 68 + d4] = *(const float4*)&Vb[rr * 64 + d4];
        }
        __syncthreads();

        // --- scores: s[i] = Q[r] . K[q+4i] ---
        float s[16];
#pragma unroll
        for (int i = 0; i < 16; ++i) s[i] = 0.f;
#pragma unroll
        for (int d4 = 0; d4 < 16; ++d4) {
            float4 qv = *(const float4*)&sQ[r * 64 + d4 * 4];
#pragma unroll
            for (int i = 0; i < 16; ++i) {
                float4 kv = *(const float4*)&sK[(q + 4 * i) * 68 + d4 * 4];
                s[i] += qv.x * kv.x + qv.y * kv.y + qv.z * kv.z + qv.w * kv.w;
            }
        }
        if (kt == qt) {   // causal mask inside diagonal tile
#pragma unroll
            for (int i = 0; i < 16; ++i)
                if (q + 4 * i > r) s[i] = -1e30f;
        }

        // --- online softmax (4 lanes per row, shuffle reduce) ---
        float mt = s[0];
#pragma unroll
        for (int i = 1; i < 16; ++i) mt = fmaxf(mt, s[i]);
        mt = fmaxf(mt, __shfl_xor_sync(0xffffffffu, mt, 1));
        mt = fmaxf(mt, __shfl_xor_sync(0xffffffffu, mt, 2));
        float mn   = fmaxf(m, mt);
        float corr = __expf(m - mn);
        float p[16];
        float psum = 0.f;
#pragma unroll
        for (int i = 0; i < 16; ++i) { p[i] = __expf(s[i] - mn); psum += p[i]; }
        psum += __shfl_xor_sync(0xffffffffu, psum, 1);
        psum += __shfl_xor_sync(0xffffffffu, psum, 2);
        l = l * corr + psum;
        m = mn;
#pragma unroll
        for (int j = 0; j < 16; ++j) ctxa[j] *= corr;

        __syncthreads();            // everyone done reading sK as K
#pragma unroll
        for (int i = 0; i < 16; ++i) sK[r * 68 + (q + 4 * i)] = p[i];
        __syncthreads();            // P visible

        // --- ctx += P[r] @ V ---
#pragma unroll
        for (int c = 0; c < 64; ++c) {
            float pv = sK[r * 68 + c];
            const float* vrow = &sV[c * 68 + q * 16];
            float4 v0 = *(const float4*)&vrow[0];
            float4 v1 = *(const float4*)&vrow[4];
            float4 v2 = *(const float4*)&vrow[8];
            float4 v3 = *(const float4*)&vrow[12];
            ctxa[0]  += pv * v0.x; ctxa[1]  += pv * v0.y;
            ctxa[2]  += pv * v0.z; ctxa[3]  += pv * v0.w;
            ctxa[4]  += pv * v1.x; ctxa[5]  += pv * v1.y;
            ctxa[6]  += pv * v1.z; ctxa[7]  += pv * v1.w;
            ctxa[8]  += pv * v2.x; ctxa[9]  += pv * v2.y;
            ctxa[10] += pv * v2.z; ctxa[11] += pv * v2.w;
            ctxa[12] += pv * v3.x; ctxa[13] += pv * v3.y;
            ctxa[14] += pv * v3.z; ctxa[15] += pv * v3.w;
        }
    }

    // normalize, stage via sQ, coalesced store in [B][S][D] layout
    float inv = 1.f / l;
    __syncthreads();
#pragma unroll
    for (int j = 0; j < 16; ++j) sQ[r * 64 + q * 16 + j] = ctxa[j] * inv;
    __syncthreads();

    const int b_ = bh >> 4;
    const int h  = bh & 15;
    float* outB = ctx + ((size_t)(b_ * Sc + qt * 64)) * Dc + h * HDc;
#pragma unroll
    for (int it = 0; it < 4; ++it) {
        int i  = tid + it * 256;
        int rr = i >> 4;
        int d4 = (i & 15) << 2;
        *(float4*)&outB[(size_t)rr * Dc + d4] = *(const float4*)&sQ[rr * 64 + d4];
    }
}

// ---------------------------------------------------------------------------
extern "C" void kernel_launch(void* const* d_in, const int* in_sizes, int n_in,
                              void* d_out, int out_size)
{
    const float* query = (const float*)d_in[0];
    const float* key   = (const float*)d_in[1];
    const float* value = (const float*)d_in[2];
    // d_in[3] = mask (causal tril) — applied analytically in attn_kernel
    const float* Wq = (const float*)d_in[4];
    const float* bq = (const float*)d_in[5];
    const float* Wk = (const float*)d_in[6];
    const float* bk = (const float*)d_in[7];
    const float* Wv = (const float*)d_in[8];
    const float* bv = (const float*)d_in[9];
    const float* Wo = (const float*)d_in[10];
    const float* bo = (const float*)d_in[11];
    float* out = (float*)d_out;

    float *qp, *kp, *vp, *cp;
    cudaGetSymbolAddress((void**)&qp, g_Q);
    cudaGetSymbolAddress((void**)&kp, g_K);
    cudaGetSymbolAddress((void**)&vp, g_V);
    cudaGetSymbolAddress((void**)&cp, g_ctx);

    dim3 ggrid(Dc / 128, Mc / 128);   // (8, 32)
    gemm_bias_kernel<true><<<ggrid, 256>>>(query, Wq, bq, qp);
    gemm_bias_kernel<true><<<ggrid, 256>>>(key,   Wk, bk, kp);
    gemm_bias_kernel<true><<<ggrid, 256>>>(value, Wv, bv, vp);

    cudaFuncSetAttribute(attn_kernel,
                         cudaFuncAttributeMaxDynamicSharedMemorySize,
                         ATTN_SMEM_BYTES);
    attn_kernel<<<dim3(Sc / 64, Bc * Hc), 256, ATTN_SMEM_BYTES>>>(qp, kp, vp, cp);

    gemm_bias_kernel<false><<<ggrid, 256>>>(cp, Wo, bo, out);
}

// round 4
// speedup vs baseline: 1.1802x; 1.1802x over previous
#include <cuda_runtime.h>
#include <cstdint>

// Problem constants
constexpr int Bc  = 2;
constexpr int Sc  = 2048;
constexpr int Dc  = 1024;
constexpr int Hc  = 16;
constexpr int HDc = 64;
constexpr int Mc  = Bc * Sc;   // 4096 rows for the projection GEMMs

// Scratch (allocation-free rule: __device__ globals). 4 x 16MB = 64MB.
__device__ float g_Q[Bc * Hc * Sc * HDc];
__device__ float g_K[Bc * Hc * Sc * HDc];
__device__ float g_V[Bc * Hc * Sc * HDc];
__device__ float g_ctx[Mc * Dc];

// One dynamic-shared symbol for the whole TU.
extern __shared__ __align__(1024) char dyn_smem[];

// ---------------------------------------------------------------------------
// helpers
// ---------------------------------------------------------------------------
__device__ __forceinline__ uint32_t f2tf32(float x) {
    uint32_t u;
    asm("cvt.rna.tf32.f32 %0, %1;" : "=r"(u) : "f"(x));
    return u;
}

__device__ __forceinline__ void mma_tf32(float* d, const uint32_t* a,
                                         const uint32_t* b) {
    asm volatile(
        "mma.sync.aligned.m16n8k8.row.col.f32.tf32.tf32.f32 "
        "{%0,%1,%2,%3}, {%4,%5,%6,%7}, {%8,%9}, {%0,%1,%2,%3};"
        : "+f"(d[0]), "+f"(d[1]), "+f"(d[2]), "+f"(d[3])
        : "r"(a[0]), "r"(a[1]), "r"(a[2]), "r"(a[3]), "r"(b[0]), "r"(b[1]));
}

// ---------------------------------------------------------------------------
// tf32 mma.sync GEMM: out[m][n] = sum_k A[m][k]*W[n][k] + bias[n]
// M=4096, N=1024, K=1024. CTA tile 128x128, K chunks of 32, double-buffered
// smem (stride-36 padding -> conflict-free fragment LDS), register prefetch.
// 8 warps as 2(m) x 4(n); warp tile 64x32; m16n8k8 -> 4x4 mma grid per warp.
// PERMUTE=true -> head-major store out[((b*H+h)*S+s)*64 + hd]
// ---------------------------------------------------------------------------
constexpr int GK         = 1024;
constexpr int KC         = 32;
constexpr int NCHUNK     = GK / KC;                 // 32
constexpr int LDS_STRIDE = 36;                      // 32 data + 4 pad floats
constexpr int TILE_FLTS  = 128 * LDS_STRIDE;        // 4608 floats per tile
constexpr int STAGE_FLTS = 2 * TILE_FLTS;           // A + B
constexpr int GEMM_SMEM  = 2 * STAGE_FLTS * 4;      // 73728 bytes

template <bool PERMUTE>
__global__ __launch_bounds__(256, 1) void gemm_mma_kernel(
    const float* __restrict__ A, const float* __restrict__ W,
    const float* __restrict__ bias, float* __restrict__ out)
{
    uint32_t* sm = (uint32_t*)dyn_smem;
    const int tid  = threadIdx.x;
    const int wid  = tid >> 5;
    const int lane = tid & 31;
    const int wm   = wid >> 2;          // 0..1
    const int wn   = wid & 3;           // 0..3
    const int bn   = blockIdx.x << 7;
    const int bm   = blockIdx.y << 7;

    const int lrow = lane >> 2;         // 0..7
    const int lcol = lane & 3;          // 0..3

    const float* Ab = A + (size_t)bm * GK;
    const float* Wb = W + (size_t)bn * GK;

    // per-thread load coords (4 iterations cover 128x32 of A and of B)
    const int g_row = tid >> 3;          // 0..31 (+32 per iter)
    const int g_c4  = (tid & 7) << 2;    // 0,4,...,28

    float4 pfA[4], pfB[4];
    auto gload = [&](int c) {
        const int kb = c * KC + g_c4;
#pragma unroll
        for (int t = 0; t < 4; ++t) {
            int row = g_row + t * 32;
            pfA[t] = *(const float4*)(Ab + (size_t)row * GK + kb);
            pfB[t] = *(const float4*)(Wb + (size_t)row * GK + kb);
        }
    };
    auto sstore = [&](int s) {
        uint32_t* sa = sm + s * STAGE_FLTS;
        uint32_t* sb = sa + TILE_FLTS;
#pragma unroll
        for (int t = 0; t < 4; ++t) {
            int row = g_row + t * 32;
            int off = row * LDS_STRIDE + g_c4;
            sa[off + 0] = f2tf32(pfA[t].x); sa[off + 1] = f2tf32(pfA[t].y);
            sa[off + 2] = f2tf32(pfA[t].z); sa[off + 3] = f2tf32(pfA[t].w);
            sb[off + 0] = f2tf32(pfB[t].x); sb[off + 1] = f2tf32(pfB[t].y);
            sb[off + 2] = f2tf32(pfB[t].z); sb[off + 3] = f2tf32(pfB[t].w);
        }
    };

    float acc[4][4][4];
#pragma unroll
    for (int i = 0; i < 4; ++i)
#pragma unroll
        for (int j = 0; j < 4; ++j)
#pragma unroll
            for (int r = 0; r < 4; ++r) acc[i][j][r] = 0.f;

    gload(0); sstore(0);
    __syncthreads();

    for (int c = 0; c < NCHUNK; ++c) {
        if (c + 1 < NCHUNK) gload(c + 1);

        const uint32_t* sa = sm + (c & 1) * STAGE_FLTS;
        const uint32_t* sb = sa + TILE_FLTS;
#pragma unroll
        for (int ks = 0; ks < 4; ++ks) {
            const int k0 = ks * 8;
            uint32_t af[4][4], bf[4][2];
#pragma unroll
            for (int mi = 0; mi < 4; ++mi) {
                int r0 = wm * 64 + mi * 16 + lrow;
                const uint32_t* p = sa + r0 * LDS_STRIDE + k0 + lcol;
                af[mi][0] = p[0];
                af[mi][1] = p[8 * LDS_STRIDE];
                af[mi][2] = p[4];
                af[mi][3] = p[8 * LDS_STRIDE + 4];
            }
#pragma unroll
            for (int ni = 0; ni < 4; ++ni) {
                int n0 = wn * 32 + ni * 8 + lrow;
                const uint32_t* p = sb + n0 * LDS_STRIDE + k0 + lcol;
                bf[ni][0] = p[0];
                bf[ni][1] = p[4];
            }
#pragma unroll
            for (int mi = 0; mi < 4; ++mi)
#pragma unroll
                for (int ni = 0; ni < 4; ++ni)
                    mma_tf32(acc[mi][ni], af[mi], bf[ni]);
        }

        __syncthreads();
        if (c + 1 < NCHUNK) {
            sstore((c + 1) & 1);
            __syncthreads();
        }
    }

    // epilogue: bias + (optional) head-permute, float2 stores
#pragma unroll
    for (int mi = 0; mi < 4; ++mi) {
        const int row0 = bm + wm * 64 + mi * 16 + lrow;
        const int row1 = row0 + 8;
#pragma unroll
        for (int ni = 0; ni < 4; ++ni) {
            const int col = bn + wn * 32 + ni * 8 + 2 * lcol;
            float2 bv = *(const float2*)&bias[col];
            float2 o0 = { acc[mi][ni][0] + bv.x, acc[mi][ni][1] + bv.y };
            float2 o1 = { acc[mi][ni][2] + bv.x, acc[mi][ni][3] + bv.y };
            if (PERMUTE) {
                const int h  = col >> 6;
                const int hd = col & 63;
                {
                    int b_ = row0 >> 11, s = row0 & 2047;
                    *(float2*)&out[(((size_t)(b_ * Hc + h) * Sc + s) << 6) + hd] = o0;
                }
                {
                    int b_ = row1 >> 11, s = row1 & 2047;
                    *(float2*)&out[(((size_t)(b_ * Hc + h) * Sc + s) << 6) + hd] = o1;
                }
            } else {
                *(float2*)&out[(size_t)row0 * Dc + col] = o0;
                *(float2*)&out[(size_t)row1 * Dc + col] = o1;
            }
        }
    }
}

// ---------------------------------------------------------------------------
// Flash attention (causal), fp32 — unchanged from R1 (passing version).
// ---------------------------------------------------------------------------
constexpr int ATTN_SMEM_FLOATS = 64 * 64 + 64 * 68 + 64 * 68;   // 12800
constexpr int ATTN_SMEM_BYTES  = ATTN_SMEM_FLOATS * 4;          // 51200

__global__ __launch_bounds__(256) void attn_kernel(
    const float* __restrict__ Q, const float* __restrict__ Kt,
    const float* __restrict__ V, float* __restrict__ ctx)
{
    float* smem = (float*)dyn_smem;
    float* sQ = smem;                 // stride 64
    float* sK = smem + 64 * 64;       // stride 68 (also holds P)
    float* sV = sK + 64 * 68;         // stride 68

    const int tid = threadIdx.x;
    const int r   = tid >> 2;
    const int q   = tid & 3;
    const int qt  = blockIdx.x;
    const int bh  = blockIdx.y;

    const float scale = 0.125f;

    const float* Qb = Q + ((size_t)bh * Sc + qt * 64) * HDc;
#pragma unroll
    for (int it = 0; it < 4; ++it) {
        int i  = tid + it * 256;
        int rr = i >> 4;
        int d4 = (i & 15) << 2;
        float4 v = *(const float4*)&Qb[rr * 64 + d4];
        v.x *= scale; v.y *= scale; v.z *= scale; v.w *= scale;
        *(float4*)&sQ[rr * 64 + d4] = v;
    }

    float m = -1e30f, l = 0.f;
    float ctxa[16];
#pragma unroll
    for (int j = 0; j < 16; ++j) ctxa[j] = 0.f;

    for (int kt = 0; kt <= qt; ++kt) {
        const float* Kb = Kt + ((size_t)bh * Sc + kt * 64) * HDc;
        const float* Vb = V  + ((size_t)bh * Sc + kt * 64) * HDc;

        __syncthreads();
#pragma unroll
        for (int it = 0; it < 4; ++it) {
            int i  = tid + it * 256;
            int rr = i >> 4;
            int d4 = (i & 15) << 2;
            *(float4*)&sK[rr * 68 + d4] = *(const float4*)&Kb[rr * 64 + d4];
            *(float4*)&sV[rr * 68 + d4] = *(const float4*)&Vb[rr * 64 + d4];
        }
        __syncthreads();

        float s[16];
#pragma unroll
        for (int i = 0; i < 16; ++i) s[i] = 0.f;
#pragma unroll
        for (int d4 = 0; d4 < 16; ++d4) {
            float4 qv = *(const float4*)&sQ[r * 64 + d4 * 4];
#pragma unroll
            for (int i = 0; i < 16; ++i) {
                float4 kv = *(const float4*)&sK[(q + 4 * i) * 68 + d4 * 4];
                s[i] += qv.x * kv.x + qv.y * kv.y + qv.z * kv.z + qv.w * kv.w;
            }
        }
        if (kt == qt) {
#pragma unroll
            for (int i = 0; i < 16; ++i)
                if (q + 4 * i > r) s[i] = -1e30f;
        }

        float mt = s[0];
#pragma unroll
        for (int i = 1; i < 16; ++i) mt = fmaxf(mt, s[i]);
        mt = fmaxf(mt, __shfl_xor_sync(0xffffffffu, mt, 1));
        mt = fmaxf(mt, __shfl_xor_sync(0xffffffffu, mt, 2));
        float mn   = fmaxf(m, mt);
        float corr = __expf(m - mn);
        float p[16];
        float psum = 0.f;
#pragma unroll
        for (int i = 0; i < 16; ++i) { p[i] = __expf(s[i] - mn); psum += p[i]; }
        psum += __shfl_xor_sync(0xffffffffu, psum, 1);
        psum += __shfl_xor_sync(0xffffffffu, psum, 2);
        l = l * corr + psum;
        m = mn;
#pragma unroll
        for (int j = 0; j < 16; ++j) ctxa[j] *= corr;

        __syncthreads();
#pragma unroll
        for (int i = 0; i < 16; ++i) sK[r * 68 + (q + 4 * i)] = p[i];
        __syncthreads();

#pragma unroll
        for (int c = 0; c < 64; ++c) {
            float pv = sK[r * 68 + c];
            const float* vrow = &sV[c * 68 + q * 16];
            float4 v0 = *(const float4*)&vrow[0];
            float4 v1 = *(const float4*)&vrow[4];
            float4 v2 = *(const float4*)&vrow[8];
            float4 v3 = *(const float4*)&vrow[12];
            ctxa[0]  += pv * v0.x; ctxa[1]  += pv * v0.y;
            ctxa[2]  += pv * v0.z; ctxa[3]  += pv * v0.w;
            ctxa[4]  += pv * v1.x; ctxa[5]  += pv * v1.y;
            ctxa[6]  += pv * v1.z; ctxa[7]  += pv * v1.w;
            ctxa[8]  += pv * v2.x; ctxa[9]  += pv * v2.y;
            ctxa[10] += pv * v2.z; ctxa[11] += pv * v2.w;
            ctxa[12] += pv * v3.x; ctxa[13] += pv * v3.y;
            ctxa[14] += pv * v3.z; ctxa[15] += pv * v3.w;
        }
    }

    float inv = 1.f / l;
    __syncthreads();
#pragma unroll
    for (int j = 0; j < 16; ++j) sQ[r * 64 + q * 16 + j] = ctxa[j] * inv;
    __syncthreads();

    const int b_ = bh >> 4;
    const int h  = bh & 15;
    float* outB = ctx + ((size_t)(b_ * Sc + qt * 64)) * Dc + h * HDc;
#pragma unroll
    for (int it = 0; it < 4; ++it) {
        int i  = tid + it * 256;
        int rr = i >> 4;
        int d4 = (i & 15) << 2;
        *(float4*)&outB[(size_t)rr * Dc + d4] = *(const float4*)&sQ[rr * 64 + d4];
    }
}

// ---------------------------------------------------------------------------
extern "C" void kernel_launch(void* const* d_in, const int* in_sizes, int n_in,
                              void* d_out, int out_size)
{
    const float* query = (const float*)d_in[0];
    const float* key   = (const float*)d_in[1];
    const float* value = (const float*)d_in[2];
    // d_in[3] = mask (causal tril) — applied analytically in attn_kernel
    const float* Wq = (const float*)d_in[4];
    const float* bq = (const float*)d_in[5];
    const float* Wk = (const float*)d_in[6];
    const float* bk = (const float*)d_in[7];
    const float* Wv = (const float*)d_in[8];
    const float* bv = (const float*)d_in[9];
    const float* Wo = (const float*)d_in[10];
    const float* bo = (const float*)d_in[11];
    float* out = (float*)d_out;

    float *qp, *kp, *vp, *cp;
    cudaGetSymbolAddress((void**)&qp, g_Q);
    cudaGetSymbolAddress((void**)&kp, g_K);
    cudaGetSymbolAddress((void**)&vp, g_V);
    cudaGetSymbolAddress((void**)&cp, g_ctx);

    cudaFuncSetAttribute(gemm_mma_kernel<true>,
                         cudaFuncAttributeMaxDynamicSharedMemorySize, GEMM_SMEM);
    cudaFuncSetAttribute(gemm_mma_kernel<false>,
                         cudaFuncAttributeMaxDynamicSharedMemorySize, GEMM_SMEM);
    cudaFuncSetAttribute(attn_kernel,
                         cudaFuncAttributeMaxDynamicSharedMemorySize, ATTN_SMEM_BYTES);

    dim3 ggrid(Dc / 128, Mc / 128);   // (8, 32)
    gemm_mma_kernel<true><<<ggrid, 256, GEMM_SMEM>>>(query, Wq, bq, qp);
    gemm_mma_kernel<true><<<ggrid, 256, GEMM_SMEM>>>(key,   Wk, bk, kp);
    gemm_mma_kernel<true><<<ggrid, 256, GEMM_SMEM>>>(value, Wv, bv, vp);

    attn_kernel<<<dim3(Sc / 64, Bc * Hc), 256, ATTN_SMEM_BYTES>>>(qp, kp, vp, cp);

    gemm_mma_kernel<false><<<ggrid, 256, GEMM_SMEM>>>(cp, Wo, bo, out);
}

// round 5
// speedup vs baseline: 4.7310x; 4.0088x over previous
#include <cuda_runtime.h>
#include <cstdint>

// Problem constants
constexpr int Bc  = 2;
constexpr int Sc  = 2048;
constexpr int Dc  = 1024;
constexpr int Hc  = 16;
constexpr int HDc = 64;
constexpr int Mc  = Bc * Sc;   // 4096 rows for the projection GEMMs

// Scratch (allocation-free rule: __device__ globals). 4 x 16MB = 64MB.
__device__ float g_Q[Bc * Hc * Sc * HDc];
__device__ float g_K[Bc * Hc * Sc * HDc];
__device__ float g_V[Bc * Hc * Sc * HDc];
__device__ float g_ctx[Mc * Dc];

// One dynamic-shared symbol for the whole TU.
extern __shared__ __align__(1024) char dyn_smem[];

// ---------------------------------------------------------------------------
// helpers
// ---------------------------------------------------------------------------
__device__ __forceinline__ uint32_t f2tf32(float x) {
    uint32_t u;
    asm("cvt.rna.tf32.f32 %0, %1;" : "=r"(u) : "f"(x));
    return u;
}

__device__ __forceinline__ void mma_tf32(float* d, const uint32_t* a,
                                         const uint32_t* b) {
    asm volatile(
        "mma.sync.aligned.m16n8k8.row.col.f32.tf32.tf32.f32 "
        "{%0,%1,%2,%3}, {%4,%5,%6,%7}, {%8,%9}, {%0,%1,%2,%3};"
        : "+f"(d[0]), "+f"(d[1]), "+f"(d[2]), "+f"(d[3])
        : "r"(a[0]), "r"(a[1]), "r"(a[2]), "r"(a[3]), "r"(b[0]), "r"(b[1]));
}

// ---------------------------------------------------------------------------
// tf32 mma.sync GEMM (unchanged from R4, verified): out = A @ W^T + bias
// ---------------------------------------------------------------------------
constexpr int GK         = 1024;
constexpr int KC         = 32;
constexpr int NCHUNK     = GK / KC;                 // 32
constexpr int LDS_STRIDE = 36;                      // 32 data + 4 pad floats
constexpr int TILE_FLTS  = 128 * LDS_STRIDE;        // 4608 floats per tile
constexpr int STAGE_FLTS = 2 * TILE_FLTS;           // A + B
constexpr int GEMM_SMEM  = 2 * STAGE_FLTS * 4;      // 73728 bytes

template <bool PERMUTE>
__global__ __launch_bounds__(256, 1) void gemm_mma_kernel(
    const float* __restrict__ A, const float* __restrict__ W,
    const float* __restrict__ bias, float* __restrict__ out)
{
    uint32_t* sm = (uint32_t*)dyn_smem;
    const int tid  = threadIdx.x;
    const int wid  = tid >> 5;
    const int lane = tid & 31;
    const int wm   = wid >> 2;          // 0..1
    const int wn   = wid & 3;           // 0..3
    const int bn   = blockIdx.x << 7;
    const int bm   = blockIdx.y << 7;

    const int lrow = lane >> 2;         // 0..7
    const int lcol = lane & 3;          // 0..3

    const float* Ab = A + (size_t)bm * GK;
    const float* Wb = W + (size_t)bn * GK;

    const int g_row = tid >> 3;          // 0..31 (+32 per iter)
    const int g_c4  = (tid & 7) << 2;    // 0,4,...,28

    float4 pfA[4], pfB[4];
    auto gload = [&](int c) {
        const int kb = c * KC + g_c4;
#pragma unroll
        for (int t = 0; t < 4; ++t) {
            int row = g_row + t * 32;
            pfA[t] = *(const float4*)(Ab + (size_t)row * GK + kb);
            pfB[t] = *(const float4*)(Wb + (size_t)row * GK + kb);
        }
    };
    auto sstore = [&](int s) {
        uint32_t* sa = sm + s * STAGE_FLTS;
        uint32_t* sb = sa + TILE_FLTS;
#pragma unroll
        for (int t = 0; t < 4; ++t) {
            int row = g_row + t * 32;
            int off = row * LDS_STRIDE + g_c4;
            sa[off + 0] = f2tf32(pfA[t].x); sa[off + 1] = f2tf32(pfA[t].y);
            sa[off + 2] = f2tf32(pfA[t].z); sa[off + 3] = f2tf32(pfA[t].w);
            sb[off + 0] = f2tf32(pfB[t].x); sb[off + 1] = f2tf32(pfB[t].y);
            sb[off + 2] = f2tf32(pfB[t].z); sb[off + 3] = f2tf32(pfB[t].w);
        }
    };

    float acc[4][4][4];
#pragma unroll
    for (int i = 0; i < 4; ++i)
#pragma unroll
        for (int j = 0; j < 4; ++j)
#pragma unroll
            for (int r = 0; r < 4; ++r) acc[i][j][r] = 0.f;

    gload(0); sstore(0);
    __syncthreads();

    for (int c = 0; c < NCHUNK; ++c) {
        if (c + 1 < NCHUNK) gload(c + 1);

        const uint32_t* sa = sm + (c & 1) * STAGE_FLTS;
        const uint32_t* sb = sa + TILE_FLTS;
#pragma unroll
        for (int ks = 0; ks < 4; ++ks) {
            const int k0 = ks * 8;
            uint32_t af[4][4], bf[4][2];
#pragma unroll
            for (int mi = 0; mi < 4; ++mi) {
                int r0 = wm * 64 + mi * 16 + lrow;
                const uint32_t* p = sa + r0 * LDS_STRIDE + k0 + lcol;
                af[mi][0] = p[0];
                af[mi][1] = p[8 * LDS_STRIDE];
                af[mi][2] = p[4];
                af[mi][3] = p[8 * LDS_STRIDE + 4];
            }
#pragma unroll
            for (int ni = 0; ni < 4; ++ni) {
                int n0 = wn * 32 + ni * 8 + lrow;
                const uint32_t* p = sb + n0 * LDS_STRIDE + k0 + lcol;
                bf[ni][0] = p[0];
                bf[ni][1] = p[4];
            }
#pragma unroll
            for (int mi = 0; mi < 4; ++mi)
#pragma unroll
                for (int ni = 0; ni < 4; ++ni)
                    mma_tf32(acc[mi][ni], af[mi], bf[ni]);
        }

        __syncthreads();
        if (c + 1 < NCHUNK) {
            sstore((c + 1) & 1);
            __syncthreads();
        }
    }

#pragma unroll
    for (int mi = 0; mi < 4; ++mi) {
        const int row0 = bm + wm * 64 + mi * 16 + lrow;
        const int row1 = row0 + 8;
#pragma unroll
        for (int ni = 0; ni < 4; ++ni) {
            const int col = bn + wn * 32 + ni * 8 + 2 * lcol;
            float2 bv = *(const float2*)&bias[col];
            float2 o0 = { acc[mi][ni][0] + bv.x, acc[mi][ni][1] + bv.y };
            float2 o1 = { acc[mi][ni][2] + bv.x, acc[mi][ni][3] + bv.y };
            if (PERMUTE) {
                const int h  = col >> 6;
                const int hd = col & 63;
                {
                    int b_ = row0 >> 11, s = row0 & 2047;
                    *(float2*)&out[(((size_t)(b_ * Hc + h) * Sc + s) << 6) + hd] = o0;
                }
                {
                    int b_ = row1 >> 11, s = row1 & 2047;
                    *(float2*)&out[(((size_t)(b_ * Hc + h) * Sc + s) << 6) + hd] = o1;
                }
            } else {
                *(float2*)&out[(size_t)row0 * Dc + col] = o0;
                *(float2*)&out[(size_t)row1 * Dc + col] = o1;
            }
        }
    }
}

// ---------------------------------------------------------------------------
// Flash attention (causal) with tf32 mma.sync.
// Block = 256 threads (8 warps as 2m x 4n), 64-row q-tile per CTA.
// S = Q@K^T via MMA -> smem -> online softmax (R1 pattern) -> P (tf32) in
// smem -> O += P@V via MMA with per-row rescale.
// Strides: sQ/sS 68 (a-frag banks 4r+k, conflict-free),
//          sK/sV 72 (b-frag banks 8k+n, conflict-free).
// ---------------------------------------------------------------------------
constexpr int STR_Q = 68;
constexpr int STR_S = 68;
constexpr int STR_K = 72;
constexpr int ATTN_SMEM_FLOATS = 64 * STR_Q + 64 * STR_S + 2 * 64 * STR_K + 64;
constexpr int ATTN_SMEM_BYTES  = ATTN_SMEM_FLOATS * 4;   // 71936

__global__ __launch_bounds__(256, 1) void attn_mma_kernel(
    const float* __restrict__ Q, const float* __restrict__ Kt,
    const float* __restrict__ V, float* __restrict__ ctx)
{
    float* smf = (float*)dyn_smem;
    float*    sS  = smf + 64 * STR_Q;
    uint32_t* sQu = (uint32_t*)smf;
    uint32_t* sSu = (uint32_t*)sS;
    uint32_t* sKu = (uint32_t*)(sS + 64 * STR_S);
    uint32_t* sVu = sKu + 64 * STR_K;
    float*    sCorr = (float*)(sVu + 64 * STR_K);

    const int tid  = threadIdx.x;
    const int wid  = tid >> 5;
    const int lane = tid & 31;
    const int lrow = lane >> 2;
    const int lcol = lane & 3;
    const int wm   = wid >> 2;          // 0..1
    const int wn   = wid & 3;           // 0..3

    const int qt = gridDim.x - 1 - blockIdx.x;   // long CTAs first
    const int bh = blockIdx.y;

    const int r = tid >> 2;             // softmax row owner
    const int q = tid & 3;

    // load Q tile, scaled by 1/8, converted to tf32
    const float* Qb = Q + ((size_t)bh * Sc + qt * 64) * HDc;
#pragma unroll
    for (int it = 0; it < 4; ++it) {
        int i  = tid + it * 256;
        int rr = i >> 4;
        int d4 = (i & 15) << 2;
        float4 v = *(const float4*)&Qb[rr * 64 + d4];
        uint4 u = { f2tf32(v.x * 0.125f), f2tf32(v.y * 0.125f),
                    f2tf32(v.z * 0.125f), f2tf32(v.w * 0.125f) };
        *(uint4*)&sQu[rr * STR_Q + d4] = u;
    }

    float m_r = -1e30f, l_r = 0.f;
    float oacc[2][2][4];
#pragma unroll
    for (int mi = 0; mi < 2; ++mi)
#pragma unroll
        for (int ni = 0; ni < 2; ++ni)
#pragma unroll
            for (int t = 0; t < 4; ++t) oacc[mi][ni][t] = 0.f;

    for (int kt = 0; kt <= qt; ++kt) {
        __syncthreads();   // prev PV reads done; Q visible on iter 0

        const float* Kb = Kt + ((size_t)bh * Sc + kt * 64) * HDc;
        const float* Vb = V  + ((size_t)bh * Sc + kt * 64) * HDc;
#pragma unroll
        for (int it = 0; it < 4; ++it) {
            int i  = tid + it * 256;
            int rr = i >> 4;
            int d4 = (i & 15) << 2;
            float4 kv = *(const float4*)&Kb[rr * 64 + d4];
            float4 vv = *(const float4*)&Vb[rr * 64 + d4];
            uint4 ku = { f2tf32(kv.x), f2tf32(kv.y), f2tf32(kv.z), f2tf32(kv.w) };
            uint4 vu = { f2tf32(vv.x), f2tf32(vv.y), f2tf32(vv.z), f2tf32(vv.w) };
            *(uint4*)&sKu[rr * STR_K + d4] = ku;
            *(uint4*)&sVu[rr * STR_K + d4] = vu;
        }
        __syncthreads();

        // ---- S = Q @ K^T (warp tile 32x16: 2 mi x 2 ni) ----
        float sacc[2][2][4];
#pragma unroll
        for (int mi = 0; mi < 2; ++mi)
#pragma unroll
            for (int ni = 0; ni < 2; ++ni)
#pragma unroll
                for (int t = 0; t < 4; ++t) sacc[mi][ni][t] = 0.f;

#pragma unroll
        for (int ks = 0; ks < 8; ++ks) {
            const int k0 = ks * 8;
            uint32_t af[2][4], bf[2][2];
#pragma unroll
            for (int mi = 0; mi < 2; ++mi) {
                int r0 = wm * 32 + mi * 16 + lrow;
                const uint32_t* p = sQu + r0 * STR_Q + k0 + lcol;
                af[mi][0] = p[0];
                af[mi][1] = p[8 * STR_Q];
                af[mi][2] = p[4];
                af[mi][3] = p[8 * STR_Q + 4];
            }
#pragma unroll
            for (int ni = 0; ni < 2; ++ni) {
                int n0 = wn * 16 + ni * 8 + lrow;
                const uint32_t* p = sKu + n0 * STR_K + k0 + lcol;
                bf[ni][0] = p[0];
                bf[ni][1] = p[4];
            }
#pragma unroll
            for (int mi = 0; mi < 2; ++mi)
#pragma unroll
                for (int ni = 0; ni < 2; ++ni)
                    mma_tf32(sacc[mi][ni], af[mi], bf[ni]);
        }
        // stage S (fp32) to smem
#pragma unroll
        for (int mi = 0; mi < 2; ++mi) {
            int r0 = wm * 32 + mi * 16 + lrow;
#pragma unroll
            for (int ni = 0; ni < 2; ++ni) {
                int c0 = wn * 16 + ni * 8 + 2 * lcol;
                *(float2*)&sS[r0 * STR_S + c0] =
                    make_float2(sacc[mi][ni][0], sacc[mi][ni][1]);
                *(float2*)&sS[(r0 + 8) * STR_S + c0] =
                    make_float2(sacc[mi][ni][2], sacc[mi][ni][3]);
            }
        }
        __syncthreads();

        // ---- online softmax (thread owns row r, cols q+4i) ----
        float s[16];
#pragma unroll
        for (int i = 0; i < 16; ++i) s[i] = sS[r * STR_S + q + 4 * i];
        if (kt == qt) {
#pragma unroll
            for (int i = 0; i < 16; ++i)
                if (q + 4 * i > r) s[i] = -1e30f;
        }
        float mt = s[0];
#pragma unroll
        for (int i = 1; i < 16; ++i) mt = fmaxf(mt, s[i]);
        mt = fmaxf(mt, __shfl_xor_sync(0xffffffffu, mt, 1));
        mt = fmaxf(mt, __shfl_xor_sync(0xffffffffu, mt, 2));
        float mn   = fmaxf(m_r, mt);
        float corr = __expf(m_r - mn);
        float psum = 0.f;
#pragma unroll
        for (int i = 0; i < 16; ++i) {
            float p = __expf(s[i] - mn);
            psum += p;
            sSu[r * STR_S + q + 4 * i] = f2tf32(p);
        }
        psum += __shfl_xor_sync(0xffffffffu, psum, 1);
        psum += __shfl_xor_sync(0xffffffffu, psum, 2);
        l_r = l_r * corr + psum;
        m_r = mn;
        if (q == 0) sCorr[r] = corr;
        __syncthreads();

        // ---- rescale O, then O += P @ V ----
#pragma unroll
        for (int mi = 0; mi < 2; ++mi) {
            int r0 = wm * 32 + mi * 16 + lrow;
            float ca = sCorr[r0];
            float cb = sCorr[r0 + 8];
#pragma unroll
            for (int ni = 0; ni < 2; ++ni) {
                oacc[mi][ni][0] *= ca; oacc[mi][ni][1] *= ca;
                oacc[mi][ni][2] *= cb; oacc[mi][ni][3] *= cb;
            }
        }
#pragma unroll
        for (int ks = 0; ks < 8; ++ks) {
            const int k0 = ks * 8;
            uint32_t af[2][4], bf[2][2];
#pragma unroll
            for (int mi = 0; mi < 2; ++mi) {
                int r0 = wm * 32 + mi * 16 + lrow;
                const uint32_t* p = sSu + r0 * STR_S + k0 + lcol;
                af[mi][0] = p[0];
                af[mi][1] = p[8 * STR_S];
                af[mi][2] = p[4];
                af[mi][3] = p[8 * STR_S + 4];
            }
#pragma unroll
            for (int ni = 0; ni < 2; ++ni) {
                int n0 = wn * 16 + ni * 8 + lrow;
                const uint32_t* p = sVu + (k0 + lcol) * STR_K + n0;
                bf[ni][0] = p[0];
                bf[ni][1] = p[4 * STR_K];
            }
#pragma unroll
            for (int mi = 0; mi < 2; ++mi)
#pragma unroll
                for (int ni = 0; ni < 2; ++ni)
                    mma_tf32(oacc[mi][ni], af[mi], bf[ni]);
        }
    }

    // epilogue: normalize by 1/l and store to ctx [B][S][D]
    if (q == 0) sCorr[r] = 1.f / l_r;
    __syncthreads();

    const int b_ = bh >> 4;
    const int h  = bh & 15;
    float* outB = ctx + ((size_t)(b_ * Sc + qt * 64)) * Dc + h * HDc;
#pragma unroll
    for (int mi = 0; mi < 2; ++mi) {
        int r0 = wm * 32 + mi * 16 + lrow;
        float ia = sCorr[r0];
        float ib = sCorr[r0 + 8];
#pragma unroll
        for (int ni = 0; ni < 2; ++ni) {
            int c0 = wn * 16 + ni * 8 + 2 * lcol;
            *(float2*)&outB[(size_t)r0 * Dc + c0] =
                make_float2(oacc[mi][ni][0] * ia, oacc[mi][ni][1] * ia);
            *(float2*)&outB[(size_t)(r0 + 8) * Dc + c0] =
                make_float2(oacc[mi][ni][2] * ib, oacc[mi][ni][3] * ib);
        }
    }
}

// ---------------------------------------------------------------------------
extern "C" void kernel_launch(void* const* d_in, const int* in_sizes, int n_in,
                              void* d_out, int out_size)
{
    const float* query = (const float*)d_in[0];
    const float* key   = (const float*)d_in[1];
    const float* value = (const float*)d_in[2];
    // d_in[3] = mask (causal tril) — applied analytically in attn kernel
    const float* Wq = (const float*)d_in[4];
    const float* bq = (const float*)d_in[5];
    const float* Wk = (const float*)d_in[6];
    const float* bk = (const float*)d_in[7];
    const float* Wv = (const float*)d_in[8];
    const float* bv = (const float*)d_in[9];
    const float* Wo = (const float*)d_in[10];
    const float* bo = (const float*)d_in[11];
    float* out = (float*)d_out;

    float *qp, *kp, *vp, *cp;
    cudaGetSymbolAddress((void**)&qp, g_Q);
    cudaGetSymbolAddress((void**)&kp, g_K);
    cudaGetSymbolAddress((void**)&vp, g_V);
    cudaGetSymbolAddress((void**)&cp, g_ctx);

    cudaFuncSetAttribute(gemm_mma_kernel<true>,
                         cudaFuncAttributeMaxDynamicSharedMemorySize, GEMM_SMEM);
    cudaFuncSetAttribute(gemm_mma_kernel<false>,
                         cudaFuncAttributeMaxDynamicSharedMemorySize, GEMM_SMEM);
    cudaFuncSetAttribute(attn_mma_kernel,
                         cudaFuncAttributeMaxDynamicSharedMemorySize, ATTN_SMEM_BYTES);

    dim3 ggrid(Dc / 128, Mc / 128);   // (8, 32)
    gemm_mma_kernel<true><<<ggrid, 256, GEMM_SMEM>>>(query, Wq, bq, qp);
    gemm_mma_kernel<true><<<ggrid, 256, GEMM_SMEM>>>(key,   Wk, bk, kp);
    gemm_mma_kernel<true><<<ggrid, 256, GEMM_SMEM>>>(value, Wv, bv, vp);

    attn_mma_kernel<<<dim3(Sc / 64, Bc * Hc), 256, ATTN_SMEM_BYTES>>>(qp, kp, vp, cp);

    gemm_mma_kernel<false><<<ggrid, 256, GEMM_SMEM>>>(cp, Wo, bo, out);
}

// round 6
// speedup vs baseline: 4.7598x; 1.0061x over previous
#include <cuda_runtime.h>
#include <cstdint>

// Problem constants
constexpr int Bc  = 2;
constexpr int Sc  = 2048;
constexpr int Dc  = 1024;
constexpr int Hc  = 16;
constexpr int HDc = 64;
constexpr int Mc  = Bc * Sc;

// Scratch (allocation-free rule: __device__ globals). 4 x 16MB = 64MB.
__device__ float g_Q[Bc * Hc * Sc * HDc];
__device__ float g_K[Bc * Hc * Sc * HDc];
__device__ float g_V[Bc * Hc * Sc * HDc];
__device__ float g_ctx[Mc * Dc];

// One dynamic-shared symbol for the whole TU.
extern __shared__ __align__(1024) char dyn_smem[];

// ---------------------------------------------------------------------------
// helpers
// ---------------------------------------------------------------------------
__device__ __forceinline__ uint32_t smem_u32(const void* p) {
    uint32_t a;
    asm("{ .reg .u64 t; cvta.to.shared.u64 t, %1; cvt.u32.u64 %0, t; }"
        : "=r"(a) : "l"(p));
    return a;
}

__device__ __forceinline__ uint32_t f2tf32(float x) {
    uint32_t u;
    asm("cvt.rna.tf32.f32 %0, %1;" : "=r"(u) : "f"(x));
    return u;
}

__device__ __forceinline__ void mma_tf32(float* d, const uint32_t* a,
                                         const uint32_t* b) {
    asm volatile(
        "mma.sync.aligned.m16n8k8.row.col.f32.tf32.tf32.f32 "
        "{%0,%1,%2,%3}, {%4,%5,%6,%7}, {%8,%9}, {%0,%1,%2,%3};"
        : "+f"(d[0]), "+f"(d[1]), "+f"(d[2]), "+f"(d[3])
        : "r"(a[0]), "r"(a[1]), "r"(a[2]), "r"(a[3]), "r"(b[0]), "r"(b[1]));
}

__device__ __forceinline__ void cp_async16(uint32_t saddr, const void* g) {
    asm volatile("cp.async.cg.shared.global [%0], [%1], 16;"
                 :: "r"(saddr), "l"(g));
}
#define CP_COMMIT() asm volatile("cp.async.commit_group;" ::: "memory")
#define CP_WAIT0()  asm volatile("cp.async.wait_group 0;" ::: "memory")
#define CP_WAIT1()  asm volatile("cp.async.wait_group 1;" ::: "memory")

// ---------------------------------------------------------------------------
// tf32 mma.sync GEMM, cp.async 3-stage pipeline: out = A @ W^T + bias
// M=4096, N=1024, K=1024. CTA tile 128x128, K chunks of 32. Raw fp32 in smem
// (stride 36), cvt.rna at fragment load. One sync per chunk. 2 CTAs/SM.
// ---------------------------------------------------------------------------
constexpr int GK      = 1024;
constexpr int KC      = 32;
constexpr int NCHUNK  = GK / KC;        // 32
constexpr int GSTR    = 36;             // floats per smem row
constexpr int GTILE   = 128 * GSTR;     // 4608 floats
constexpr int GSTAGE  = 2 * GTILE;      // A + B
constexpr int GEMM_SMEM = 3 * GSTAGE * 4;  // 110592 bytes

template <bool PERMUTE>
__global__ __launch_bounds__(256, 2) void gemm_mma_kernel(
    const float* __restrict__ A, const float* __restrict__ W,
    const float* __restrict__ bias, float* __restrict__ out)
{
    const float* smf = (const float*)dyn_smem;
    const uint32_t smem_base = smem_u32(dyn_smem);

    const int tid  = threadIdx.x;
    const int wid  = tid >> 5;
    const int lane = tid & 31;
    const int wm   = wid >> 2;          // 0..1
    const int wn   = wid & 3;           // 0..3
    const int bn   = blockIdx.x << 7;
    const int bm   = blockIdx.y << 7;
    const int lrow = lane >> 2;
    const int lcol = lane & 3;

    const float* Ab = A + (size_t)bm * GK;
    const float* Wb = W + (size_t)bn * GK;

    const int g_row = tid >> 3;          // 0..31 (+32 per iter)
    const int g_c4  = (tid & 7) << 2;    // 0..28

    auto issue = [&](int c, int s) {
        const uint32_t base = smem_base + (uint32_t)s * GSTAGE * 4;
        const int kb = c * KC + g_c4;
#pragma unroll
        for (int t = 0; t < 4; ++t) {
            int row = g_row + t * 32;
            cp_async16(base + (uint32_t)(row * GSTR + g_c4) * 4,
                       Ab + (size_t)row * GK + kb);
            cp_async16(base + (uint32_t)(GTILE + row * GSTR + g_c4) * 4,
                       Wb + (size_t)row * GK + kb);
        }
        CP_COMMIT();
    };

    float acc[4][4][4];
#pragma unroll
    for (int i = 0; i < 4; ++i)
#pragma unroll
        for (int j = 0; j < 4; ++j)
#pragma unroll
            for (int r = 0; r < 4; ++r) acc[i][j][r] = 0.f;

    issue(0, 0);
    issue(1, 1);

    int st = 0;
    for (int c = 0; c < NCHUNK; ++c) {
        if (c < NCHUNK - 1) { CP_WAIT1(); } else { CP_WAIT0(); }
        __syncthreads();
        if (c + 2 < NCHUNK) {
            int s2 = st + 2; if (s2 >= 3) s2 -= 3;
            issue(c + 2, s2);
        }

        const float* sa = smf + st * GSTAGE;
        const float* sb = sa + GTILE;
#pragma unroll
        for (int ks = 0; ks < 4; ++ks) {
            const int k0 = ks * 8;
            uint32_t af[4][4], bf[4][2];
#pragma unroll
            for (int mi = 0; mi < 4; ++mi) {
                int r0 = wm * 64 + mi * 16 + lrow;
                const float* p = sa + r0 * GSTR + k0 + lcol;
                af[mi][0] = f2tf32(p[0]);
                af[mi][1] = f2tf32(p[8 * GSTR]);
                af[mi][2] = f2tf32(p[4]);
                af[mi][3] = f2tf32(p[8 * GSTR + 4]);
            }
#pragma unroll
            for (int ni = 0; ni < 4; ++ni) {
                int n0 = wn * 32 + ni * 8 + lrow;
                const float* p = sb + n0 * GSTR + k0 + lcol;
                bf[ni][0] = f2tf32(p[0]);
                bf[ni][1] = f2tf32(p[4]);
            }
#pragma unroll
            for (int mi = 0; mi < 4; ++mi)
#pragma unroll
                for (int ni = 0; ni < 4; ++ni)
                    mma_tf32(acc[mi][ni], af[mi], bf[ni]);
        }
        ++st; if (st == 3) st = 0;
    }

#pragma unroll
    for (int mi = 0; mi < 4; ++mi) {
        const int row0 = bm + wm * 64 + mi * 16 + lrow;
        const int row1 = row0 + 8;
#pragma unroll
        for (int ni = 0; ni < 4; ++ni) {
            const int col = bn + wn * 32 + ni * 8 + 2 * lcol;
            float2 bv = *(const float2*)&bias[col];
            float2 o0 = { acc[mi][ni][0] + bv.x, acc[mi][ni][1] + bv.y };
            float2 o1 = { acc[mi][ni][2] + bv.x, acc[mi][ni][3] + bv.y };
            if (PERMUTE) {
                const int h  = col >> 6;
                const int hd = col & 63;
                {
                    int b_ = row0 >> 11, s = row0 & 2047;
                    *(float2*)&out[(((size_t)(b_ * Hc + h) * Sc + s) << 6) + hd] = o0;
                }
                {
                    int b_ = row1 >> 11, s = row1 & 2047;
                    *(float2*)&out[(((size_t)(b_ * Hc + h) * Sc + s) << 6) + hd] = o1;
                }
            } else {
                *(float2*)&out[(size_t)row0 * Dc + col] = o0;
                *(float2*)&out[(size_t)row1 * Dc + col] = o1;
            }
        }
    }
}

// ---------------------------------------------------------------------------
// Flash attention (causal), tf32 mma.sync. 512 threads, q-tile 128 rows,
// k-tile 64. Warps 4m x 4n (warp tile 32x16). K/V double-buffered via
// cp.async (raw fp32, cvt at b-frag load). Q staged once, k-interleaved
// (LDS.64 a-frags). S staged fp32, P staged tf32 (as R5).
// ---------------------------------------------------------------------------
constexpr int STR_Q = 68;   // interleaved tf32
constexpr int STR_S = 68;   // S fp32 / P tf32
constexpr int STR_K = 68;   // raw fp32
constexpr int STR_V = 72;   // raw fp32
constexpr int OFF_Q = 0;
constexpr int OFF_S = OFF_Q + 128 * STR_Q;               // 8704
constexpr int OFF_K = OFF_S + 128 * STR_S;               // 17408
constexpr int OFF_V = OFF_K + 2 * 64 * STR_K;            // 26112
constexpr int OFF_C = OFF_V + 2 * 64 * STR_V;            // 35328
constexpr int ATTN_SMEM_BYTES = (OFF_C + 128) * 4;       // 141824

__global__ __launch_bounds__(512, 1) void attn_mma_kernel(
    const float* __restrict__ Q, const float* __restrict__ Kt,
    const float* __restrict__ V, float* __restrict__ ctx)
{
    float* smf = (float*)dyn_smem;
    const uint32_t smem_base = smem_u32(dyn_smem);

    uint32_t* sQu   = (uint32_t*)smf + OFF_Q;
    float*    sS    = smf + OFF_S;
    uint32_t* sSu   = (uint32_t*)sS;
    float*    sCorr = smf + OFF_C;

    const int tid  = threadIdx.x;
    const int wid  = tid >> 5;
    const int lane = tid & 31;
    const int lrow = lane >> 2;
    const int lcol = lane & 3;
    const int wm   = wid >> 2;          // 0..3
    const int wn   = wid & 3;           // 0..3

    const int qt = gridDim.x - 1 - blockIdx.x;   // long CTAs first
    const int bh = blockIdx.y;

    const int r = tid >> 2;             // softmax row owner, 0..127
    const int q = tid & 3;

    // ---- stage Q (scaled, tf32, k-interleaved) ----
    const float* Qb = Q + ((size_t)bh * Sc + qt * 128) * HDc;
#pragma unroll
    for (int it = 0; it < 4; ++it) {
        int i  = tid + it * 512;        // 0..2047
        int rr = i >> 4;                // 0..127
        int d4 = (i & 15) << 2;
        float4 v = *(const float4*)&Qb[rr * 64 + d4];
        int base = rr * STR_Q + (d4 & ~7) + ((d4 >> 2) & 1);
        sQu[base + 0] = f2tf32(v.x * 0.125f);
        sQu[base + 2] = f2tf32(v.y * 0.125f);
        sQu[base + 4] = f2tf32(v.z * 0.125f);
        sQu[base + 6] = f2tf32(v.w * 0.125f);
    }

    auto issue_kv = [&](int kt, int bs) {
        const float* Kb = Kt + ((size_t)bh * Sc + kt * 64) * HDc;
        const float* Vb = V  + ((size_t)bh * Sc + kt * 64) * HDc;
#pragma unroll
        for (int it = 0; it < 2; ++it) {
            int i  = tid + it * 512;    // 0..1023
            int rr = i >> 4;            // 0..63
            int d4 = (i & 15) << 2;
            cp_async16(smem_base + (uint32_t)(OFF_K + bs * 64 * STR_K +
                                              rr * STR_K + d4) * 4,
                       Kb + rr * 64 + d4);
            cp_async16(smem_base + (uint32_t)(OFF_V + bs * 64 * STR_V +
                                              rr * STR_V + d4) * 4,
                       Vb + rr * 64 + d4);
        }
        CP_COMMIT();
    };

    float m_r = -1e30f, l_r = 0.f;
    float oacc[2][2][4];
#pragma unroll
    for (int mi = 0; mi < 2; ++mi)
#pragma unroll
        for (int ni = 0; ni < 2; ++ni)
#pragma unroll
            for (int t = 0; t < 4; ++t) oacc[mi][ni][t] = 0.f;

    const int nkt = 2 * qt + 2;
    issue_kv(0, 0);

    for (int kt = 0; kt < nkt; ++kt) {
        const int bs = kt & 1;
        CP_WAIT0();
        __syncthreads();                 // K/V(kt) visible; prev iter done
        if (kt + 1 < nkt) issue_kv(kt + 1, bs ^ 1);

        const float* sKr = smf + OFF_K + bs * 64 * STR_K;
        const float* sVr = smf + OFF_V + bs * 64 * STR_V;

        // ---- S = Q @ K^T ----
        float sacc[2][2][4];
#pragma unroll
        for (int mi = 0; mi < 2; ++mi)
#pragma unroll
            for (int ni = 0; ni < 2; ++ni)
#pragma unroll
                for (int t = 0; t < 4; ++t) sacc[mi][ni][t] = 0.f;

#pragma unroll
        for (int ks = 0; ks < 8; ++ks) {
            const int k0 = ks * 8;
            uint32_t af[2][4], bf[2][2];
#pragma unroll
            for (int mi = 0; mi < 2; ++mi) {
                int r0 = wm * 32 + mi * 16 + lrow;
                const uint32_t* p = sQu + r0 * STR_Q + k0 + 2 * lcol;
                uint2 lo = *(const uint2*)p;
                uint2 hi = *(const uint2*)(p + 8 * STR_Q);
                af[mi][0] = lo.x; af[mi][2] = lo.y;
                af[mi][1] = hi.x; af[mi][3] = hi.y;
            }
#pragma unroll
            for (int ni = 0; ni < 2; ++ni) {
                int n0 = wn * 16 + ni * 8 + lrow;
                const float* p = sKr + n0 * STR_K + k0 + lcol;
                bf[ni][0] = f2tf32(p[0]);
                bf[ni][1] = f2tf32(p[4]);
            }
#pragma unroll
            for (int mi = 0; mi < 2; ++mi)
#pragma unroll
                for (int ni = 0; ni < 2; ++ni)
                    mma_tf32(sacc[mi][ni], af[mi], bf[ni]);
        }
        // stage S (fp32)
#pragma unroll
        for (int mi = 0; mi < 2; ++mi) {
            int r0 = wm * 32 + mi * 16 + lrow;
#pragma unroll
            for (int ni = 0; ni < 2; ++ni) {
                int c0 = wn * 16 + ni * 8 + 2 * lcol;
                *(float2*)&sS[r0 * STR_S + c0] =
                    make_float2(sacc[mi][ni][0], sacc[mi][ni][1]);
                *(float2*)&sS[(r0 + 8) * STR_S + c0] =
                    make_float2(sacc[mi][ni][2], sacc[mi][ni][3]);
            }
        }
        __syncthreads();

        // ---- online softmax ----
        float s[16];
#pragma unroll
        for (int i = 0; i < 16; ++i) s[i] = sS[r * STR_S + q + 4 * i];
        if (kt >= 2 * qt) {               // diagonal-crossing tiles
            const int coff = kt * 64 - qt * 128;
#pragma unroll
            for (int i = 0; i < 16; ++i)
                if (coff + q + 4 * i > r) s[i] = -1e30f;
        }
        float mt = s[0];
#pragma unroll
        for (int i = 1; i < 16; ++i) mt = fmaxf(mt, s[i]);
        mt = fmaxf(mt, __shfl_xor_sync(0xffffffffu, mt, 1));
        mt = fmaxf(mt, __shfl_xor_sync(0xffffffffu, mt, 2));
        float mn   = fmaxf(m_r, mt);
        float corr = __expf(m_r - mn);
        float psum = 0.f;
#pragma unroll
        for (int i = 0; i < 16; ++i) {
            float p = __expf(s[i] - mn);
            psum += p;
            sSu[r * STR_S + q + 4 * i] = f2tf32(p);
        }
        psum += __shfl_xor_sync(0xffffffffu, psum, 1);
        psum += __shfl_xor_sync(0xffffffffu, psum, 2);
        l_r = l_r * corr + psum;
        m_r = mn;
        if (q == 0) sCorr[r] = corr;
        __syncthreads();

        // ---- O = O*corr + P @ V ----
#pragma unroll
        for (int mi = 0; mi < 2; ++mi) {
            int r0 = wm * 32 + mi * 16 + lrow;
            float ca = sCorr[r0];
            float cb = sCorr[r0 + 8];
#pragma unroll
            for (int ni = 0; ni < 2; ++ni) {
                oacc[mi][ni][0] *= ca; oacc[mi][ni][1] *= ca;
                oacc[mi][ni][2] *= cb; oacc[mi][ni][3] *= cb;
            }
        }
#pragma unroll
        for (int ks = 0; ks < 8; ++ks) {
            const int k0 = ks * 8;
            uint32_t af[2][4], bf[2][2];
#pragma unroll
            for (int mi = 0; mi < 2; ++mi) {
                int r0 = wm * 32 + mi * 16 + lrow;
                const uint32_t* p = sSu + r0 * STR_S + k0 + lcol;
                af[mi][0] = p[0];
                af[mi][1] = p[8 * STR_S];
                af[mi][2] = p[4];
                af[mi][3] = p[8 * STR_S + 4];
            }
#pragma unroll
            for (int ni = 0; ni < 2; ++ni) {
                int n0 = wn * 16 + ni * 8 + lrow;
                const float* p = sVr + (k0 + lcol) * STR_V + n0;
                bf[ni][0] = f2tf32(p[0]);
                bf[ni][1] = f2tf32(p[4 * STR_V]);
            }
#pragma unroll
            for (int mi = 0; mi < 2; ++mi)
#pragma unroll
                for (int ni = 0; ni < 2; ++ni)
                    mma_tf32(oacc[mi][ni], af[mi], bf[ni]);
        }
    }

    // epilogue: normalize and store to ctx [B][S][D]
    if (q == 0) sCorr[r] = 1.f / l_r;
    __syncthreads();

    const int b_ = bh >> 4;
    const int h  = bh & 15;
    float* outB = ctx + ((size_t)(b_ * Sc + qt * 128)) * Dc + h * HDc;
#pragma unroll
    for (int mi = 0; mi < 2; ++mi) {
        int r0 = wm * 32 + mi * 16 + lrow;
        float ia = sCorr[r0];
        float ib = sCorr[r0 + 8];
#pragma unroll
        for (int ni = 0; ni < 2; ++ni) {
            int c0 = wn * 16 + ni * 8 + 2 * lcol;
            *(float2*)&outB[(size_t)r0 * Dc + c0] =
                make_float2(oacc[mi][ni][0] * ia, oacc[mi][ni][1] * ia);
            *(float2*)&outB[(size_t)(r0 + 8) * Dc + c0] =
                make_float2(oacc[mi][ni][2] * ib, oacc[mi][ni][3] * ib);
        }
    }
}

// ---------------------------------------------------------------------------
extern "C" void kernel_launch(void* const* d_in, const int* in_sizes, int n_in,
                              void* d_out, int out_size)
{
    const float* query = (const float*)d_in[0];
    const float* key   = (const float*)d_in[1];
    const float* value = (const float*)d_in[2];
    // d_in[3] = mask (causal tril) — applied analytically in attn kernel
    const float* Wq = (const float*)d_in[4];
    const float* bq = (const float*)d_in[5];
    const float* Wk = (const float*)d_in[6];
    const float* bk = (const float*)d_in[7];
    const float* Wv = (const float*)d_in[8];
    const float* bv = (const float*)d_in[9];
    const float* Wo = (const float*)d_in[10];
    const float* bo = (const float*)d_in[11];
    float* out = (float*)d_out;

    float *qp, *kp, *vp, *cp;
    cudaGetSymbolAddress((void**)&qp, g_Q);
    cudaGetSymbolAddress((void**)&kp, g_K);
    cudaGetSymbolAddress((void**)&vp, g_V);
    cudaGetSymbolAddress((void**)&cp, g_ctx);

    cudaFuncSetAttribute(gemm_mma_kernel<true>,
                         cudaFuncAttributeMaxDynamicSharedMemorySize, GEMM_SMEM);
    cudaFuncSetAttribute(gemm_mma_kernel<false>,
                         cudaFuncAttributeMaxDynamicSharedMemorySize, GEMM_SMEM);
    cudaFuncSetAttribute(attn_mma_kernel,
                         cudaFuncAttributeMaxDynamicSharedMemorySize,
                         ATTN_SMEM_BYTES);

    dim3 ggrid(Dc / 128, Mc / 128);   // (8, 32)
    gemm_mma_kernel<true><<<ggrid, 256, GEMM_SMEM>>>(query, Wq, bq, qp);
    gemm_mma_kernel<true><<<ggrid, 256, GEMM_SMEM>>>(key,   Wk, bk, kp);
    gemm_mma_kernel<true><<<ggrid, 256, GEMM_SMEM>>>(value, Wv, bv, vp);

    attn_mma_kernel<<<dim3(Sc / 128, Bc * Hc), 512, ATTN_SMEM_BYTES>>>(qp, kp, vp, cp);

    gemm_mma_kernel<false><<<ggrid, 256, GEMM_SMEM>>>(cp, Wo, bo, out);
}

// round 7
// speedup vs baseline: 5.3669x; 1.1275x over previous
#include <cuda_runtime.h>
#include <cstdint>

// Problem constants
constexpr int Bc  = 2;
constexpr int Sc  = 2048;
constexpr int Dc  = 1024;
constexpr int Hc  = 16;
constexpr int HDc = 64;
constexpr int Mc  = Bc * Sc;

// Scratch (allocation-free rule: __device__ globals). 4 x 16MB = 64MB.
__device__ float g_Q[Bc * Hc * Sc * HDc];
__device__ float g_K[Bc * Hc * Sc * HDc];
__device__ float g_V[Bc * Hc * Sc * HDc];
__device__ float g_ctx[Mc * Dc];

// One dynamic-shared symbol for the whole TU.
extern __shared__ __align__(1024) char dyn_smem[];

// ---------------------------------------------------------------------------
// helpers
// ---------------------------------------------------------------------------
__device__ __forceinline__ uint32_t smem_u32(const void* p) {
    uint32_t a;
    asm("{ .reg .u64 t; cvta.to.shared.u64 t, %1; cvt.u32.u64 %0, t; }"
        : "=r"(a) : "l"(p));
    return a;
}

__device__ __forceinline__ uint32_t f2tf32(float x) {
    uint32_t u;
    asm("cvt.rna.tf32.f32 %0, %1;" : "=r"(u) : "f"(x));
    return u;
}

__device__ __forceinline__ void mma_tf32(float* d, const uint32_t* a,
                                         const uint32_t* b) {
    asm volatile(
        "mma.sync.aligned.m16n8k8.row.col.f32.tf32.tf32.f32 "
        "{%0,%1,%2,%3}, {%4,%5,%6,%7}, {%8,%9}, {%0,%1,%2,%3};"
        : "+f"(d[0]), "+f"(d[1]), "+f"(d[2]), "+f"(d[3])
        : "r"(a[0]), "r"(a[1]), "r"(a[2]), "r"(a[3]), "r"(b[0]), "r"(b[1]));
}

__device__ __forceinline__ void cp_async16(uint32_t saddr, const void* g) {
    asm volatile("cp.async.cg.shared.global [%0], [%1], 16;"
                 :: "r"(saddr), "l"(g));
}
#define CP_COMMIT() asm volatile("cp.async.commit_group;" ::: "memory")
#define CP_WAIT0()  asm volatile("cp.async.wait_group 0;" ::: "memory")
#define CP_WAIT1()  asm volatile("cp.async.wait_group 1;" ::: "memory")

// ---------------------------------------------------------------------------
// tf32 mma.sync GEMM, cp.async 3-stage pipeline, BATCHED over blockIdx.z:
// out[z] = A[z] @ W[z]^T + bias[z].  CTA tile 128x128, K chunks of 32.
// ---------------------------------------------------------------------------
constexpr int GK      = 1024;
constexpr int KC      = 32;
constexpr int NCHUNK  = GK / KC;        // 32
constexpr int GSTR    = 36;             // floats per smem row
constexpr int GTILE   = 128 * GSTR;     // 4608 floats
constexpr int GSTAGE  = 2 * GTILE;      // A + B
constexpr int GEMM_SMEM = 3 * GSTAGE * 4;  // 110592 bytes

struct GemmTriple {
    const float* A[3];
    const float* W[3];
    const float* bias[3];
    float*       out[3];
};

template <bool PERMUTE>
__global__ __launch_bounds__(256, 2) void gemm_mma_kernel(GemmTriple args)
{
    const float* smf = (const float*)dyn_smem;
    const uint32_t smem_base = smem_u32(dyn_smem);

    const int z = blockIdx.z;
    const float* __restrict__ A    = args.A[z];
    const float* __restrict__ W    = args.W[z];
    const float* __restrict__ bias = args.bias[z];
    float* __restrict__ out        = args.out[z];

    const int tid  = threadIdx.x;
    const int wid  = tid >> 5;
    const int lane = tid & 31;
    const int wm   = wid >> 2;          // 0..1
    const int wn   = wid & 3;           // 0..3
    const int bn   = blockIdx.x << 7;
    const int bm   = blockIdx.y << 7;
    const int lrow = lane >> 2;
    const int lcol = lane & 3;

    const float* Ab = A + (size_t)bm * GK;
    const float* Wb = W + (size_t)bn * GK;

    const int g_row = tid >> 3;          // 0..31 (+32 per iter)
    const int g_c4  = (tid & 7) << 2;    // 0..28

    auto issue = [&](int c, int s) {
        const uint32_t base = smem_base + (uint32_t)s * GSTAGE * 4;
        const int kb = c * KC + g_c4;
#pragma unroll
        for (int t = 0; t < 4; ++t) {
            int row = g_row + t * 32;
            cp_async16(base + (uint32_t)(row * GSTR + g_c4) * 4,
                       Ab + (size_t)row * GK + kb);
            cp_async16(base + (uint32_t)(GTILE + row * GSTR + g_c4) * 4,
                       Wb + (size_t)row * GK + kb);
        }
        CP_COMMIT();
    };

    float acc[4][4][4];
#pragma unroll
    for (int i = 0; i < 4; ++i)
#pragma unroll
        for (int j = 0; j < 4; ++j)
#pragma unroll
            for (int r = 0; r < 4; ++r) acc[i][j][r] = 0.f;

    issue(0, 0);
    issue(1, 1);

    int st = 0;
    for (int c = 0; c < NCHUNK; ++c) {
        if (c < NCHUNK - 1) { CP_WAIT1(); } else { CP_WAIT0(); }
        __syncthreads();
        if (c + 2 < NCHUNK) {
            int s2 = st + 2; if (s2 >= 3) s2 -= 3;
            issue(c + 2, s2);
        }

        const float* sa = smf + st * GSTAGE;
        const float* sb = sa + GTILE;
#pragma unroll
        for (int ks = 0; ks < 4; ++ks) {
            const int k0 = ks * 8;
            uint32_t af[4][4], bf[4][2];
#pragma unroll
            for (int mi = 0; mi < 4; ++mi) {
                int r0 = wm * 64 + mi * 16 + lrow;
                const float* p = sa + r0 * GSTR + k0 + lcol;
                af[mi][0] = f2tf32(p[0]);
                af[mi][1] = f2tf32(p[8 * GSTR]);
                af[mi][2] = f2tf32(p[4]);
                af[mi][3] = f2tf32(p[8 * GSTR + 4]);
            }
#pragma unroll
            for (int ni = 0; ni < 4; ++ni) {
                int n0 = wn * 32 + ni * 8 + lrow;
                const float* p = sb + n0 * GSTR + k0 + lcol;
                bf[ni][0] = f2tf32(p[0]);
                bf[ni][1] = f2tf32(p[4]);
            }
#pragma unroll
            for (int mi = 0; mi < 4; ++mi)
#pragma unroll
                for (int ni = 0; ni < 4; ++ni)
                    mma_tf32(acc[mi][ni], af[mi], bf[ni]);
        }
        ++st; if (st == 3) st = 0;
    }

#pragma unroll
    for (int mi = 0; mi < 4; ++mi) {
        const int row0 = bm + wm * 64 + mi * 16 + lrow;
        const int row1 = row0 + 8;
#pragma unroll
        for (int ni = 0; ni < 4; ++ni) {
            const int col = bn + wn * 32 + ni * 8 + 2 * lcol;
            float2 bv = *(const float2*)&bias[col];
            float2 o0 = { acc[mi][ni][0] + bv.x, acc[mi][ni][1] + bv.y };
            float2 o1 = { acc[mi][ni][2] + bv.x, acc[mi][ni][3] + bv.y };
            if (PERMUTE) {
                const int h  = col >> 6;
                const int hd = col & 63;
                {
                    int b_ = row0 >> 11, s = row0 & 2047;
                    *(float2*)&out[(((size_t)(b_ * Hc + h) * Sc + s) << 6) + hd] = o0;
                }
                {
                    int b_ = row1 >> 11, s = row1 & 2047;
                    *(float2*)&out[(((size_t)(b_ * Hc + h) * Sc + s) << 6) + hd] = o1;
                }
            } else {
                *(float2*)&out[(size_t)row0 * Dc + col] = o0;
                *(float2*)&out[(size_t)row1 * Dc + col] = o1;
            }
        }
    }
}

// ---------------------------------------------------------------------------
// Flash attention (causal), tf32 mma.sync, REGISTER-RESIDENT softmax.
// 256 threads = 8 warps; each warp owns 16 full rows (warp tile m16 x n64).
// q-tile 128, k-tile 64. S stays in accumulator fragments; row max/sum via
// quad shuffles; P a-frags for P@V built by intra-quad shuffles (exact).
// K/V double-buffered cp.async. ONE __syncthreads per k-tile.
// ---------------------------------------------------------------------------
constexpr int STR_Q = 68;   // interleaved tf32
constexpr int STR_K = 68;   // raw fp32
constexpr int STR_V = 72;   // raw fp32
constexpr int OFF_Q = 0;
constexpr int OFF_K = OFF_Q + 128 * STR_Q;               // 8704
constexpr int OFF_V = OFF_K + 2 * 64 * STR_K;            // 17408
constexpr int ATTN_SMEM_FLOATS = OFF_V + 2 * 64 * STR_V; // 26624
constexpr int ATTN_SMEM_BYTES  = ATTN_SMEM_FLOATS * 4;   // 106496

__global__ __launch_bounds__(256, 2) void attn_mma_kernel(
    const float* __restrict__ Q, const float* __restrict__ Kt,
    const float* __restrict__ V, float* __restrict__ ctx)
{
    float* smf = (float*)dyn_smem;
    const uint32_t smem_base = smem_u32(dyn_smem);

    uint32_t* sQu = (uint32_t*)smf + OFF_Q;

    const int tid  = threadIdx.x;
    const int wid  = tid >> 5;          // 0..7 -> rows wid*16..+15
    const int lane = tid & 31;
    const int lrow = lane >> 5 ? 0 : (lane >> 2);   // lane>>2
    const int lcol = lane & 3;

    const int qt = gridDim.x - 1 - blockIdx.x;   // long CTAs first
    const int bh = blockIdx.y;

    // ---- issue K/V (kt) into buffer bs ----
    auto issue_kv = [&](int kt, int bs) {
        const float* Kb = Kt + ((size_t)bh * Sc + kt * 64) * HDc;
        const float* Vb = V  + ((size_t)bh * Sc + kt * 64) * HDc;
#pragma unroll
        for (int it = 0; it < 4; ++it) {
            int i  = tid + it * 256;    // 0..1023
            int rr = i >> 4;            // 0..63
            int d4 = (i & 15) << 2;
            cp_async16(smem_base + (uint32_t)(OFF_K + bs * 64 * STR_K +
                                              rr * STR_K + d4) * 4,
                       Kb + rr * 64 + d4);
            cp_async16(smem_base + (uint32_t)(OFF_V + bs * 64 * STR_V +
                                              rr * STR_V + d4) * 4,
                       Vb + rr * 64 + d4);
        }
        CP_COMMIT();
    };

    const int nkt = 2 * qt + 2;
    issue_kv(0, 0);

    // ---- stage Q (scaled, tf32, k-interleaved) ----
    const float* Qb = Q + ((size_t)bh * Sc + qt * 128) * HDc;
#pragma unroll
    for (int it = 0; it < 8; ++it) {
        int i  = tid + it * 256;        // 0..2047
        int rr = i >> 4;                // 0..127
        int d4 = (i & 15) << 2;
        float4 v = *(const float4*)&Qb[rr * 64 + d4];
        int base = rr * STR_Q + (d4 & ~7) + ((d4 >> 2) & 1);
        sQu[base + 0] = f2tf32(v.x * 0.125f);
        sQu[base + 2] = f2tf32(v.y * 0.125f);
        sQu[base + 4] = f2tf32(v.z * 0.125f);
        sQu[base + 6] = f2tf32(v.w * 0.125f);
    }

    // per-thread state: rows r0 = qt*128 + wid*16 + lrow and r0+8
    float m0 = -1e30f, m1 = -1e30f, l0 = 0.f, l1 = 0.f;
    float oacc[8][4];
#pragma unroll
    for (int ni = 0; ni < 8; ++ni)
#pragma unroll
        for (int t = 0; t < 4; ++t) oacc[ni][t] = 0.f;

    const int row_g0 = qt * 128 + wid * 16 + lrow;
    const int row_g1 = row_g0 + 8;
    const int s1lane = (lane & 28) | (lcol >> 1);
    const int s2lane = s1lane + 2;
    const bool par   = lcol & 1;

    for (int kt = 0; kt < nkt; ++kt) {
        const int bs = kt & 1;
        CP_WAIT0();
        __syncthreads();                 // K/V(kt) visible; all done with bs^1
        if (kt + 1 < nkt) issue_kv(kt + 1, bs ^ 1);

        const float* sKr = smf + OFF_K + bs * 64 * STR_K;
        const float* sVr = smf + OFF_V + bs * 64 * STR_V;

        // ---- S = Q @ K^T  (warp tile 16 x 64 : 8 n8-tiles) ----
        float sacc[8][4];
#pragma unroll
        for (int t = 0; t < 8; ++t)
#pragma unroll
            for (int j = 0; j < 4; ++j) sacc[t][j] = 0.f;

#pragma unroll
        for (int ks = 0; ks < 8; ++ks) {
            const int k0 = ks * 8;
            uint32_t af[4];
            {
                int r0 = wid * 16 + lrow;
                const uint32_t* p = sQu + r0 * STR_Q + k0 + 2 * lcol;
                uint2 lo = *(const uint2*)p;
                uint2 hi = *(const uint2*)(p + 8 * STR_Q);
                af[0] = lo.x; af[2] = lo.y;
                af[1] = hi.x; af[3] = hi.y;
            }
#pragma unroll
            for (int ni = 0; ni < 8; ++ni) {
                int n0 = ni * 8 + lrow;
                const float* p = sKr + n0 * STR_K + k0 + lcol;
                uint32_t bf[2] = { f2tf32(p[0]), f2tf32(p[4]) };
                mma_tf32(sacc[ni], af, bf);
            }
        }

        // ---- causal mask (register) ----
        if (kt >= 2 * qt) {
            const int cbase = kt * 64;
#pragma unroll
            for (int t = 0; t < 8; ++t) {
                int c0 = cbase + t * 8 + 2 * lcol;
                if (c0 > row_g0)     sacc[t][0] = -1e30f;
                if (c0 + 1 > row_g0) sacc[t][1] = -1e30f;
                if (c0 > row_g1)     sacc[t][2] = -1e30f;
                if (c0 + 1 > row_g1) sacc[t][3] = -1e30f;
            }
        }

        // ---- online softmax, all in registers ----
        float mt0 = sacc[0][0], mt1 = sacc[0][2];
#pragma unroll
        for (int t = 0; t < 8; ++t) {
            mt0 = fmaxf(mt0, fmaxf(sacc[t][0], sacc[t][1]));
            mt1 = fmaxf(mt1, fmaxf(sacc[t][2], sacc[t][3]));
        }
        mt0 = fmaxf(mt0, __shfl_xor_sync(0xffffffffu, mt0, 1));
        mt0 = fmaxf(mt0, __shfl_xor_sync(0xffffffffu, mt0, 2));
        mt1 = fmaxf(mt1, __shfl_xor_sync(0xffffffffu, mt1, 1));
        mt1 = fmaxf(mt1, __shfl_xor_sync(0xffffffffu, mt1, 2));

        float mn0 = fmaxf(m0, mt0);
        float mn1 = fmaxf(m1, mt1);
        float c0f = __expf(m0 - mn0);
        float c1f = __expf(m1 - mn1);

        float ps0 = 0.f, ps1 = 0.f;
#pragma unroll
        for (int t = 0; t < 8; ++t) {
            sacc[t][0] = __expf(sacc[t][0] - mn0);
            sacc[t][1] = __expf(sacc[t][1] - mn0);
            sacc[t][2] = __expf(sacc[t][2] - mn1);
            sacc[t][3] = __expf(sacc[t][3] - mn1);
            ps0 += sacc[t][0] + sacc[t][1];
            ps1 += sacc[t][2] + sacc[t][3];
        }
        ps0 += __shfl_xor_sync(0xffffffffu, ps0, 1);
        ps0 += __shfl_xor_sync(0xffffffffu, ps0, 2);
        ps1 += __shfl_xor_sync(0xffffffffu, ps1, 1);
        ps1 += __shfl_xor_sync(0xffffffffu, ps1, 2);
        l0 = l0 * c0f + ps0;
        l1 = l1 * c1f + ps1;
        m0 = mn0; m1 = mn1;

        // rescale O
#pragma unroll
        for (int ni = 0; ni < 8; ++ni) {
            oacc[ni][0] *= c0f; oacc[ni][1] *= c0f;
            oacc[ni][2] *= c1f; oacc[ni][3] *= c1f;
        }

        // ---- O += P @ V : build P a-frags by quad shuffles (exact) ----
#pragma unroll
        for (int t = 0; t < 8; ++t) {        // k-block = S n8-tile t
            float t00 = __shfl_sync(0xffffffffu, sacc[t][0], s1lane);
            float t01 = __shfl_sync(0xffffffffu, sacc[t][1], s1lane);
            float t10 = __shfl_sync(0xffffffffu, sacc[t][2], s1lane);
            float t11 = __shfl_sync(0xffffffffu, sacc[t][3], s1lane);
            float u00 = __shfl_sync(0xffffffffu, sacc[t][0], s2lane);
            float u01 = __shfl_sync(0xffffffffu, sacc[t][1], s2lane);
            float u10 = __shfl_sync(0xffffffffu, sacc[t][2], s2lane);
            float u11 = __shfl_sync(0xffffffffu, sacc[t][3], s2lane);
            uint32_t af[4];
            af[0] = f2tf32(par ? t01 : t00);
            af[1] = f2tf32(par ? t11 : t10);
            af[2] = f2tf32(par ? u01 : u00);
            af[3] = f2tf32(par ? u11 : u10);

            const int k0 = t * 8;
#pragma unroll
            for (int ni = 0; ni < 8; ++ni) {
                int n0 = ni * 8 + lrow;
                const float* p = sVr + (k0 + lcol) * STR_V + n0;
                uint32_t bf[2] = { f2tf32(p[0]), f2tf32(p[4 * STR_V]) };
                mma_tf32(oacc[ni], af, bf);
            }
        }
    }

    // ---- epilogue: normalize in registers, store to ctx [B][S][D] ----
    const float i0 = 1.f / l0;
    const float i1 = 1.f / l1;
    const int b_ = bh >> 4;
    const int h  = bh & 15;
    const int r0 = qt * 128 + wid * 16 + lrow;
    float* outB = ctx + ((size_t)(b_ * Sc) + r0) * Dc + h * HDc;
#pragma unroll
    for (int ni = 0; ni < 8; ++ni) {
        int c0 = ni * 8 + 2 * lcol;
        *(float2*)&outB[c0] =
            make_float2(oacc[ni][0] * i0, oacc[ni][1] * i0);
        *(float2*)&outB[(size_t)8 * Dc + c0] =
            make_float2(oacc[ni][2] * i1, oacc[ni][3] * i1);
    }
}

// ---------------------------------------------------------------------------
extern "C" void kernel_launch(void* const* d_in, const int* in_sizes, int n_in,
                              void* d_out, int out_size)
{
    const float* query = (const float*)d_in[0];
    const float* key   = (const float*)d_in[1];
    const float* value = (const float*)d_in[2];
    // d_in[3] = mask (causal tril) — applied analytically in attn kernel
    const float* Wq = (const float*)d_in[4];
    const float* bq = (const float*)d_in[5];
    const float* Wk = (const float*)d_in[6];
    const float* bk = (const float*)d_in[7];
    const float* Wv = (const float*)d_in[8];
    const float* bv = (const float*)d_in[9];
    const float* Wo = (const float*)d_in[10];
    const float* bo = (const float*)d_in[11];
    float* out = (float*)d_out;

    float *qp, *kp, *vp, *cp;
    cudaGetSymbolAddress((void**)&qp, g_Q);
    cudaGetSymbolAddress((void**)&kp, g_K);
    cudaGetSymbolAddress((void**)&vp, g_V);
    cudaGetSymbolAddress((void**)&cp, g_ctx);

    cudaFuncSetAttribute(gemm_mma_kernel<true>,
                         cudaFuncAttributeMaxDynamicSharedMemorySize, GEMM_SMEM);
    cudaFuncSetAttribute(gemm_mma_kernel<false>,
                         cudaFuncAttributeMaxDynamicSharedMemorySize, GEMM_SMEM);
    cudaFuncSetAttribute(attn_mma_kernel,
                         cudaFuncAttributeMaxDynamicSharedMemorySize,
                         ATTN_SMEM_BYTES);

    // batched QKV projections (grid.z = 3)
    GemmTriple qkv;
    qkv.A[0] = query; qkv.A[1] = key; qkv.A[2] = value;
    qkv.W[0] = Wq;    qkv.W[1] = Wk;  qkv.W[2] = Wv;
    qkv.bias[0] = bq; qkv.bias[1] = bk; qkv.bias[2] = bv;
    qkv.out[0] = qp;  qkv.out[1] = kp;  qkv.out[2] = vp;
    gemm_mma_kernel<true><<<dim3(Dc / 128, Mc / 128, 3), 256, GEMM_SMEM>>>(qkv);

    attn_mma_kernel<<<dim3(Sc / 128, Bc * Hc), 256, ATTN_SMEM_BYTES>>>(qp, kp, vp, cp);

    // O projection
    GemmTriple og;
    og.A[0] = cp; og.W[0] = Wo; og.bias[0] = bo; og.out[0] = out;
    og.A[1] = og.A[2] = cp; og.W[1] = og.W[2] = Wo;
    og.bias[1] = og.bias[2] = bo; og.out[1] = og.out[2] = out;
    gemm_mma_kernel<false><<<dim3(Dc / 128, Mc / 128, 1), 256, GEMM_SMEM>>>(og);
}

// round 8
// speedup vs baseline: 6.3073x; 1.1752x over previous
#include <cuda_runtime.h>
#include <cstdint>

// Problem constants
constexpr int Bc  = 2;
constexpr int Sc  = 2048;
constexpr int Dc  = 1024;
constexpr int Hc  = 16;
constexpr int HDc = 64;
constexpr int Mc  = Bc * Sc;

// Scratch (__device__ globals; allocation-free rule). Total 128MB.
__device__ uint32_t g_Q[Bc * Hc * Sc * HDc];    // tf32, interleaved, pre-scaled
__device__ uint32_t g_K[Bc * Hc * Sc * HDc];    // tf32, interleaved
__device__ uint32_t g_V[Bc * Hc * Sc * HDc];    // tf32, natural
__device__ uint32_t g_ctx[Mc * Dc];             // tf32, interleaved
__device__ uint32_t g_qc[Mc * Dc];              // converted inputs
__device__ uint32_t g_kc[Mc * Dc];
__device__ uint32_t g_vc[Mc * Dc];
__device__ uint32_t g_wq[Dc * Dc];
__device__ uint32_t g_wk[Dc * Dc];
__device__ uint32_t g_wv[Dc * Dc];
__device__ uint32_t g_wo[Dc * Dc];

extern __shared__ __align__(1024) char dyn_smem[];

// ---------------------------------------------------------------------------
// helpers
// ---------------------------------------------------------------------------
__device__ __forceinline__ uint32_t smem_u32(const void* p) {
    uint32_t a;
    asm("{ .reg .u64 t; cvta.to.shared.u64 t, %1; cvt.u32.u64 %0, t; }"
        : "=r"(a) : "l"(p));
    return a;
}

__device__ __forceinline__ uint32_t f2tf32(float x) {
    uint32_t u;
    asm("cvt.rna.tf32.f32 %0, %1;" : "=r"(u) : "f"(x));
    return u;
}

__device__ __forceinline__ void mma_tf32(float* d, const uint32_t* a,
                                         const uint32_t* b) {
    asm volatile(
        "mma.sync.aligned.m16n8k8.row.col.f32.tf32.tf32.f32 "
        "{%0,%1,%2,%3}, {%4,%5,%6,%7}, {%8,%9}, {%0,%1,%2,%3};"
        : "+f"(d[0]), "+f"(d[1]), "+f"(d[2]), "+f"(d[3])
        : "r"(a[0]), "r"(a[1]), "r"(a[2]), "r"(a[3]), "r"(b[0]), "r"(b[1]));
}

__device__ __forceinline__ void cp_async16(uint32_t saddr, const void* g) {
    asm volatile("cp.async.cg.shared.global [%0], [%1], 16;"
                 :: "r"(saddr), "l"(g));
}
#define CP_COMMIT() asm volatile("cp.async.commit_group;" ::: "memory")
#define CP_WAIT0()  asm volatile("cp.async.wait_group 0;" ::: "memory")

// interleave position within an 8-group: pos(h) = ((h&3)<<1) | ((h&4)>>2)
// (layout [0,4,1,5,2,6,3,7]; pair (even h, h+1) -> (p0, p0+2))

// ---------------------------------------------------------------------------
// Prepass: fp32 -> tf32 bits, k-interleaved, for 7 matrices (row length 1024)
// ---------------------------------------------------------------------------
struct CvtArgs {
    const float4* src[7];
    uint32_t*     dst[7];
    int           n4[7];
};

__global__ __launch_bounds__(256) void cvt_kernel(CvtArgs a)
{
    const int z = blockIdx.y;
    const float4* s = a.src[z];
    uint32_t* d = a.dst[z];
    const int n4 = a.n4[z];
    const int stride = gridDim.x * blockDim.x;
    for (int i = blockIdx.x * blockDim.x + threadIdx.x; i < n4; i += stride) {
        float4 v = s[i];
        int e0   = i << 2;
        int col0 = e0 & 1023;                 // multiple of 4
        int base = e0 - (col0 & 7) + ((col0 >> 2) & 1);  // group base + sub
        d[base + 0] = f2tf32(v.x);
        d[base + 2] = f2tf32(v.y);
        d[base + 4] = f2tf32(v.z);
        d[base + 6] = f2tf32(v.w);
    }
}

// ---------------------------------------------------------------------------
// tf32 mma.sync GEMM. Operands pre-converted tf32, k-interleaved.
// CTA tile 128x128, K chunks of 32, 2-stage cp.async, GSTR=40 (perfect
// 2-phase LDS.64). No cvt in the hot loop.
// PERMUTE=true: head-major store, per-z mode (0:Q scale+ilv, 1:K ilv, 2:V nat)
// ---------------------------------------------------------------------------
constexpr int GK     = 1024;
constexpr int KC     = 32;
constexpr int NCHUNK = GK / KC;         // 32
constexpr int GSTR   = 40;              // u32 per smem row (32 data + 8 pad)
constexpr int GTILE  = 128 * GSTR;      // 5120
constexpr int GSTAGE = 2 * GTILE;       // A + B
constexpr int GEMM_SMEM = 2 * GSTAGE * 4;   // 81920 bytes

struct GemmT {
    const uint32_t* A[3];
    const uint32_t* W[3];
    const float*    bias[3];
    void*           out[3];
};

template <bool PERMUTE>
__global__ __launch_bounds__(256, 2) void gemm_mma_kernel(GemmT args)
{
    const uint32_t* smu = (const uint32_t*)dyn_smem;
    const uint32_t smem_base = smem_u32(dyn_smem);

    const int z = blockIdx.z;
    const uint32_t* __restrict__ A = args.A[z];
    const uint32_t* __restrict__ W = args.W[z];
    const float* __restrict__ bias = args.bias[z];

    const int tid  = threadIdx.x;
    const int wid  = tid >> 5;
    const int lane = tid & 31;
    const int wm   = wid >> 2;
    const int wn   = wid & 3;
    const int bn   = blockIdx.x << 7;
    const int bm   = blockIdx.y << 7;
    const int lrow = lane >> 2;
    const int lcol = lane & 3;

    const uint32_t* Ab = A + (size_t)bm * GK;
    const uint32_t* Wb = W + (size_t)bn * GK;

    const int g_row = tid >> 3;          // 0..31 (+32 per iter)
    const int g_c4  = (tid & 7) << 2;    // 0..28

    auto issue = [&](int c, int s) {
        const uint32_t base = smem_base + (uint32_t)s * GSTAGE * 4;
        const int kb = c * KC + g_c4;
#pragma unroll
        for (int t = 0; t < 4; ++t) {
            int row = g_row + t * 32;
            cp_async16(base + (uint32_t)(row * GSTR + g_c4) * 4,
                       Ab + (size_t)row * GK + kb);
            cp_async16(base + (uint32_t)(GTILE + row * GSTR + g_c4) * 4,
                       Wb + (size_t)row * GK + kb);
        }
        CP_COMMIT();
    };

    float acc[4][4][4];
#pragma unroll
    for (int i = 0; i < 4; ++i)
#pragma unroll
        for (int j = 0; j < 4; ++j)
#pragma unroll
            for (int r = 0; r < 4; ++r) acc[i][j][r] = 0.f;

    issue(0, 0);

    for (int c = 0; c < NCHUNK; ++c) {
        CP_WAIT0();
        __syncthreads();
        if (c + 1 < NCHUNK) issue(c + 1, (c + 1) & 1);

        const uint32_t* sa = smu + (c & 1) * GSTAGE;
        const uint32_t* sb = sa + GTILE;
#pragma unroll
        for (int ks = 0; ks < 4; ++ks) {
            const int k0 = ks * 8;
            uint32_t af[4][4], bf[4][2];
#pragma unroll
            for (int mi = 0; mi < 4; ++mi) {
                int r0 = wm * 64 + mi * 16 + lrow;
                const uint32_t* p = sa + r0 * GSTR + k0 + 2 * lcol;
                uint2 lo = *(const uint2*)p;
                uint2 hi = *(const uint2*)(p + 8 * GSTR);
                af[mi][0] = lo.x; af[mi][2] = lo.y;
                af[mi][1] = hi.x; af[mi][3] = hi.y;
            }
#pragma unroll
            for (int ni = 0; ni < 4; ++ni) {
                int n0 = wn * 32 + ni * 8 + lrow;
                uint2 b2 = *(const uint2*)(sb + n0 * GSTR + k0 + 2 * lcol);
                bf[ni][0] = b2.x; bf[ni][1] = b2.y;
            }
#pragma unroll
            for (int mi = 0; mi < 4; ++mi)
#pragma unroll
                for (int ni = 0; ni < 4; ++ni)
                    mma_tf32(acc[mi][ni], af[mi], bf[ni]);
        }
    }

    // epilogue
    if (PERMUTE) {
        uint32_t* out = (uint32_t*)args.out[z];
        const float scale = (z == 0) ? 0.125f : 1.f;
        const bool ilv = (z != 2);
#pragma unroll
        for (int mi = 0; mi < 4; ++mi) {
            const int row0 = bm + wm * 64 + mi * 16 + lrow;
            const int row1 = row0 + 8;
#pragma unroll
            for (int ni = 0; ni < 4; ++ni) {
                const int col = bn + wn * 32 + ni * 8 + 2 * lcol;
                float2 bv = *(const float2*)&bias[col];
                float v00 = (acc[mi][ni][0] + bv.x) * scale;
                float v01 = (acc[mi][ni][1] + bv.y) * scale;
                float v10 = (acc[mi][ni][2] + bv.x) * scale;
                float v11 = (acc[mi][ni][3] + bv.y) * scale;
                const int h  = col >> 6;
                const int hd = col & 63;
                int b0 = row0 >> 11, s0 = row0 & 2047;
                int b1 = row1 >> 11, s1 = row1 & 2047;
                size_t bi0 = ((size_t)(b0 * Hc + h) * Sc + s0) << 6;
                size_t bi1 = ((size_t)(b1 * Hc + h) * Sc + s1) << 6;
                if (ilv) {
                    int p0 = (hd & ~7) + (((hd & 3) << 1) | ((hd & 4) >> 2));
                    out[bi0 + p0]     = f2tf32(v00);
                    out[bi0 + p0 + 2] = f2tf32(v01);
                    out[bi1 + p0]     = f2tf32(v10);
                    out[bi1 + p0 + 2] = f2tf32(v11);
                } else {
                    uint2 u0 = { f2tf32(v00), f2tf32(v01) };
                    uint2 u1 = { f2tf32(v10), f2tf32(v11) };
                    *(uint2*)&out[bi0 + hd] = u0;
                    *(uint2*)&out[bi1 + hd] = u1;
                }
            }
        }
    } else {
        float* out = (float*)args.out[z];
#pragma unroll
        for (int mi = 0; mi < 4; ++mi) {
            const int row0 = bm + wm * 64 + mi * 16 + lrow;
            const int row1 = row0 + 8;
#pragma unroll
            for (int ni = 0; ni < 4; ++ni) {
                const int col = bn + wn * 32 + ni * 8 + 2 * lcol;
                float2 bv = *(const float2*)&bias[col];
                float2 o0 = { acc[mi][ni][0] + bv.x, acc[mi][ni][1] + bv.y };
                float2 o1 = { acc[mi][ni][2] + bv.x, acc[mi][ni][3] + bv.y };
                *(float2*)&out[(size_t)row0 * Dc + col] = o0;
                *(float2*)&out[(size_t)row1 * Dc + col] = o1;
            }
        }
    }
}

// ---------------------------------------------------------------------------
// Flash attention (causal), tf32 mma.sync, register-resident softmax.
// Q/K pre-converted tf32 interleaved (Q pre-scaled), V pre-converted tf32.
// All staging is cp.async; zero cvt except P. One sync per k-tile.
// ---------------------------------------------------------------------------
constexpr int STR_Q = 72;
constexpr int STR_K = 72;
constexpr int STR_V = 72;
constexpr int OFF_Q = 0;
constexpr int OFF_K = OFF_Q + 128 * STR_Q;               // 9216
constexpr int OFF_V = OFF_K + 2 * 64 * STR_K;            // 18432
constexpr int ATTN_SMEM_U32 = OFF_V + 2 * 64 * STR_V;    // 27648
constexpr int ATTN_SMEM_BYTES = ATTN_SMEM_U32 * 4;       // 110592

__global__ __launch_bounds__(256, 2) void attn_mma_kernel(
    const uint32_t* __restrict__ Q, const uint32_t* __restrict__ Kt,
    const uint32_t* __restrict__ V, uint32_t* __restrict__ ctx)
{
    uint32_t* smu = (uint32_t*)dyn_smem;
    const uint32_t smem_base = smem_u32(dyn_smem);

    const int tid  = threadIdx.x;
    const int wid  = tid >> 5;
    const int lane = tid & 31;
    const int lrow = lane >> 2;
    const int lcol = lane & 3;

    const int qt = gridDim.x - 1 - blockIdx.x;
    const int bh = blockIdx.y;

    // stage Q via cp.async (already tf32+interleaved+scaled)
    const uint32_t* Qb = Q + ((size_t)bh * Sc + qt * 128) * HDc;
#pragma unroll
    for (int it = 0; it < 8; ++it) {
        int i  = tid + it * 256;        // 0..2047 (16B chunks)
        int rr = i >> 4;
        int d4 = (i & 15) << 2;
        cp_async16(smem_base + (uint32_t)(OFF_Q + rr * STR_Q + d4) * 4,
                   Qb + rr * 64 + d4);
    }

    auto issue_kv = [&](int kt, int bs) {
        const uint32_t* Kb = Kt + ((size_t)bh * Sc + kt * 64) * HDc;
        const uint32_t* Vb = V  + ((size_t)bh * Sc + kt * 64) * HDc;
#pragma unroll
        for (int it = 0; it < 4; ++it) {
            int i  = tid + it * 256;    // 0..1023
            int rr = i >> 4;            // 0..63
            int d4 = (i & 15) << 2;
            cp_async16(smem_base + (uint32_t)(OFF_K + bs * 64 * STR_K +
                                              rr * STR_K + d4) * 4,
                       Kb + rr * 64 + d4);
            cp_async16(smem_base + (uint32_t)(OFF_V + bs * 64 * STR_V +
                                              rr * STR_V + d4) * 4,
                       Vb + rr * 64 + d4);
        }
        CP_COMMIT();
    };

    const int nkt = 2 * qt + 2;
    issue_kv(0, 0);                      // commit covers Q stage too

    float m0 = -1e30f, m1 = -1e30f, l0 = 0.f, l1 = 0.f;
    float oacc[8][4];
#pragma unroll
    for (int ni = 0; ni < 8; ++ni)
#pragma unroll
        for (int t = 0; t < 4; ++t) oacc[ni][t] = 0.f;

    const int row_g0 = qt * 128 + wid * 16 + lrow;
    const int row_g1 = row_g0 + 8;
    const int s1lane = (lane & 28) | (lcol >> 1);
    const int s2lane = s1lane + 2;
    const bool par   = lcol & 1;

    for (int kt = 0; kt < nkt; ++kt) {
        const int bs = kt & 1;
        CP_WAIT0();
        __syncthreads();
        if (kt + 1 < nkt) issue_kv(kt + 1, bs ^ 1);

        const uint32_t* sKr = smu + OFF_K + bs * 64 * STR_K;
        const uint32_t* sVr = smu + OFF_V + bs * 64 * STR_V;
        const uint32_t* sQu = smu + OFF_Q;

        // ---- S = Q @ K^T ----
        float sacc[8][4];
#pragma unroll
        for (int t = 0; t < 8; ++t)
#pragma unroll
            for (int j = 0; j < 4; ++j) sacc[t][j] = 0.f;

#pragma unroll
        for (int ks = 0; ks < 8; ++ks) {
            const int k0 = ks * 8;
            uint32_t af[4];
            {
                int r0 = wid * 16 + lrow;
                const uint32_t* p = sQu + r0 * STR_Q + k0 + 2 * lcol;
                uint2 lo = *(const uint2*)p;
                uint2 hi = *(const uint2*)(p + 8 * STR_Q);
                af[0] = lo.x; af[2] = lo.y;
                af[1] = hi.x; af[3] = hi.y;
            }
#pragma unroll
            for (int ni = 0; ni < 8; ++ni) {
                int n0 = ni * 8 + lrow;
                uint2 b2 = *(const uint2*)(sKr + n0 * STR_K + k0 + 2 * lcol);
                uint32_t bf[2] = { b2.x, b2.y };
                mma_tf32(sacc[ni], af, bf);
            }
        }

        // ---- causal mask ----
        if (kt >= 2 * qt) {
            const int cbase = kt * 64;
#pragma unroll
            for (int t = 0; t < 8; ++t) {
                int c0 = cbase + t * 8 + 2 * lcol;
                if (c0 > row_g0)     sacc[t][0] = -1e30f;
                if (c0 + 1 > row_g0) sacc[t][1] = -1e30f;
                if (c0 > row_g1)     sacc[t][2] = -1e30f;
                if (c0 + 1 > row_g1) sacc[t][3] = -1e30f;
            }
        }

        // ---- online softmax (registers) ----
        float mt0 = sacc[0][0], mt1 = sacc[0][2];
#pragma unroll
        for (int t = 0; t < 8; ++t) {
            mt0 = fmaxf(mt0, fmaxf(sacc[t][0], sacc[t][1]));
            mt1 = fmaxf(mt1, fmaxf(sacc[t][2], sacc[t][3]));
        }
        mt0 = fmaxf(mt0, __shfl_xor_sync(0xffffffffu, mt0, 1));
        mt0 = fmaxf(mt0, __shfl_xor_sync(0xffffffffu, mt0, 2));
        mt1 = fmaxf(mt1, __shfl_xor_sync(0xffffffffu, mt1, 1));
        mt1 = fmaxf(mt1, __shfl_xor_sync(0xffffffffu, mt1, 2));

        float mn0 = fmaxf(m0, mt0);
        float mn1 = fmaxf(m1, mt1);
        float c0f = __expf(m0 - mn0);
        float c1f = __expf(m1 - mn1);

        float ps0 = 0.f, ps1 = 0.f;
#pragma unroll
        for (int t = 0; t < 8; ++t) {
            sacc[t][0] = __expf(sacc[t][0] - mn0);
            sacc[t][1] = __expf(sacc[t][1] - mn0);
            sacc[t][2] = __expf(sacc[t][2] - mn1);
            sacc[t][3] = __expf(sacc[t][3] - mn1);
            ps0 += sacc[t][0] + sacc[t][1];
            ps1 += sacc[t][2] + sacc[t][3];
        }
        ps0 += __shfl_xor_sync(0xffffffffu, ps0, 1);
        ps0 += __shfl_xor_sync(0xffffffffu, ps0, 2);
        ps1 += __shfl_xor_sync(0xffffffffu, ps1, 1);
        ps1 += __shfl_xor_sync(0xffffffffu, ps1, 2);
        l0 = l0 * c0f + ps0;
        l1 = l1 * c1f + ps1;
        m0 = mn0; m1 = mn1;

#pragma unroll
        for (int ni = 0; ni < 8; ++ni) {
            oacc[ni][0] *= c0f; oacc[ni][1] *= c0f;
            oacc[ni][2] *= c1f; oacc[ni][3] *= c1f;
        }

        // ---- O += P @ V (P a-frags via quad shuffles) ----
#pragma unroll
        for (int t = 0; t < 8; ++t) {
            float t00 = __shfl_sync(0xffffffffu, sacc[t][0], s1lane);
            float t01 = __shfl_sync(0xffffffffu, sacc[t][1], s1lane);
            float t10 = __shfl_sync(0xffffffffu, sacc[t][2], s1lane);
            float t11 = __shfl_sync(0xffffffffu, sacc[t][3], s1lane);
            float u00 = __shfl_sync(0xffffffffu, sacc[t][0], s2lane);
            float u01 = __shfl_sync(0xffffffffu, sacc[t][1], s2lane);
            float u10 = __shfl_sync(0xffffffffu, sacc[t][2], s2lane);
            float u11 = __shfl_sync(0xffffffffu, sacc[t][3], s2lane);
            uint32_t af[4];
            af[0] = f2tf32(par ? t01 : t00);
            af[1] = f2tf32(par ? t11 : t10);
            af[2] = f2tf32(par ? u01 : u00);
            af[3] = f2tf32(par ? u11 : u10);

            const int k0 = t * 8;
#pragma unroll
            for (int ni = 0; ni < 8; ++ni) {
                int n0 = ni * 8 + lrow;
                const uint32_t* p = sVr + (k0 + lcol) * STR_V + n0;
                uint32_t bf[2] = { p[0], p[4 * STR_V] };
                mma_tf32(oacc[ni], af, bf);
            }
        }
    }

    // ---- epilogue: normalize, store ctx as tf32 interleaved ----
    const float i0 = 1.f / l0;
    const float i1 = 1.f / l1;
    const int b_ = bh >> 4;
    const int h  = bh & 15;
    const int r0 = qt * 128 + wid * 16 + lrow;
    uint32_t* outU = ctx + ((size_t)(b_ * Sc) + r0) * Dc + h * HDc;
    const int e = 2 * lcol;
    const int pg = ((e & 3) << 1) | ((e & 4) >> 2);   // 0,4,1,5 for lcol 0..3
#pragma unroll
    for (int ni = 0; ni < 8; ++ni) {
        int p0 = ni * 8 + pg;
        outU[p0]     = f2tf32(oacc[ni][0] * i0);
        outU[p0 + 2] = f2tf32(oacc[ni][1] * i0);
        outU[(size_t)8 * Dc + p0]     = f2tf32(oacc[ni][2] * i1);
        outU[(size_t)8 * Dc + p0 + 2] = f2tf32(oacc[ni][3] * i1);
    }
}

// ---------------------------------------------------------------------------
extern "C" void kernel_launch(void* const* d_in, const int* in_sizes, int n_in,
                              void* d_out, int out_size)
{
    const float* query = (const float*)d_in[0];
    const float* key   = (const float*)d_in[1];
    const float* value = (const float*)d_in[2];
    // d_in[3] = mask (causal tril) — applied analytically in attn kernel
    const float* Wq = (const float*)d_in[4];
    const float* bq = (const float*)d_in[5];
    const float* Wk = (const float*)d_in[6];
    const float* bk = (const float*)d_in[7];
    const float* Wv = (const float*)d_in[8];
    const float* bv = (const float*)d_in[9];
    const float* Wo = (const float*)d_in[10];
    const float* bo = (const float*)d_in[11];
    float* out = (float*)d_out;

    uint32_t *qp, *kp, *vp, *cp;
    uint32_t *qc, *kc, *vc, *wq, *wk, *wv, *wo;
    cudaGetSymbolAddress((void**)&qp, g_Q);
    cudaGetSymbolAddress((void**)&kp, g_K);
    cudaGetSymbolAddress((void**)&vp, g_V);
    cudaGetSymbolAddress((void**)&cp, g_ctx);
    cudaGetSymbolAddress((void**)&qc, g_qc);
    cudaGetSymbolAddress((void**)&kc, g_kc);
    cudaGetSymbolAddress((void**)&vc, g_vc);
    cudaGetSymbolAddress((void**)&wq, g_wq);
    cudaGetSymbolAddress((void**)&wk, g_wk);
    cudaGetSymbolAddress((void**)&wv, g_wv);
    cudaGetSymbolAddress((void**)&wo, g_wo);

    cudaFuncSetAttribute(gemm_mma_kernel<true>,
                         cudaFuncAttributeMaxDynamicSharedMemorySize, GEMM_SMEM);
    cudaFuncSetAttribute(gemm_mma_kernel<false>,
                         cudaFuncAttributeMaxDynamicSharedMemorySize, GEMM_SMEM);
    cudaFuncSetAttribute(attn_mma_kernel,
                         cudaFuncAttributeMaxDynamicSharedMemorySize,
                         ATTN_SMEM_BYTES);

    // prepass: convert + interleave inputs and weights
    CvtArgs ca;
    ca.src[0] = (const float4*)query; ca.dst[0] = qc; ca.n4[0] = Mc * Dc / 4;
    ca.src[1] = (const float4*)key;   ca.dst[1] = kc; ca.n4[1] = Mc * Dc / 4;
    ca.src[2] = (const float4*)value; ca.dst[2] = vc; ca.n4[2] = Mc * Dc / 4;
    ca.src[3] = (const float4*)Wq;    ca.dst[3] = wq; ca.n4[3] = Dc * Dc / 4;
    ca.src[4] = (const float4*)Wk;    ca.dst[4] = wk; ca.n4[4] = Dc * Dc / 4;
    ca.src[5] = (const float4*)Wv;    ca.dst[5] = wv; ca.n4[5] = Dc * Dc / 4;
    ca.src[6] = (const float4*)Wo;    ca.dst[6] = wo; ca.n4[6] = Dc * Dc / 4;
    cvt_kernel<<<dim3(512, 7), 256>>>(ca);

    // batched QKV projections
    GemmT qkv;
    qkv.A[0] = qc;  qkv.A[1] = kc;  qkv.A[2] = vc;
    qkv.W[0] = wq;  qkv.W[1] = wk;  qkv.W[2] = wv;
    qkv.bias[0] = bq; qkv.bias[1] = bk; qkv.bias[2] = bv;
    qkv.out[0] = qp;  qkv.out[1] = kp;  qkv.out[2] = vp;
    gemm_mma_kernel<true><<<dim3(Dc / 128, Mc / 128, 3), 256, GEMM_SMEM>>>(qkv);

    attn_mma_kernel<<<dim3(Sc / 128, Bc * Hc), 256, ATTN_SMEM_BYTES>>>(qp, kp, vp, cp);

    // O projection
    GemmT og;
    og.A[0] = cp; og.W[0] = wo; og.bias[0] = bo; og.out[0] = out;
    og.A[1] = og.A[2] = cp; og.W[1] = og.W[2] = wo;
    og.bias[1] = og.bias[2] = bo; og.out[1] = og.out[2] = out;
    gemm_mma_kernel<false><<<dim3(Dc / 128, Mc / 128, 1), 256, GEMM_SMEM>>>(og);
}

// round 9
// speedup vs baseline: 6.4064x; 1.0157x over previous
#include <cuda_runtime.h>
#include <cstdint>

// Problem constants
constexpr int Bc  = 2;
constexpr int Sc  = 2048;
constexpr int Dc  = 1024;
constexpr int Hc  = 16;
constexpr int HDc = 64;
constexpr int Mc  = Bc * Sc;

// Scratch (__device__ globals; allocation-free rule).
__device__ uint32_t g_Q[Bc * Hc * Sc * HDc];    // tf32, interleaved, pre-scaled
__device__ uint32_t g_K[Bc * Hc * Sc * HDc];    // tf32, interleaved
__device__ uint32_t g_V[Bc * Hc * Sc * HDc];    // tf32, TRANSPOSED [bh*64+hd][s], s-interleaved
__device__ uint32_t g_ctx[Mc * Dc];             // tf32, interleaved
__device__ uint32_t g_qc[Mc * Dc];              // converted inputs
__device__ uint32_t g_kc[Mc * Dc];
__device__ uint32_t g_vc[Mc * Dc];
__device__ uint32_t g_wq[Dc * Dc];
__device__ uint32_t g_wk[Dc * Dc];
__device__ uint32_t g_wv[Dc * Dc];
__device__ uint32_t g_wo[Dc * Dc];

extern __shared__ __align__(1024) char dyn_smem[];

// ---------------------------------------------------------------------------
// helpers
// ---------------------------------------------------------------------------
__device__ __forceinline__ uint32_t smem_u32(const void* p) {
    uint32_t a;
    asm("{ .reg .u64 t; cvta.to.shared.u64 t, %1; cvt.u32.u64 %0, t; }"
        : "=r"(a) : "l"(p));
    return a;
}

__device__ __forceinline__ uint32_t f2tf32(float x) {
    uint32_t u;
    asm("cvt.rna.tf32.f32 %0, %1;" : "=r"(u) : "f"(x));
    return u;
}

__device__ __forceinline__ void mma_tf32(float* d, const uint32_t* a,
                                         const uint32_t* b) {
    asm volatile(
        "mma.sync.aligned.m16n8k8.row.col.f32.tf32.tf32.f32 "
        "{%0,%1,%2,%3}, {%4,%5,%6,%7}, {%8,%9}, {%0,%1,%2,%3};"
        : "+f"(d[0]), "+f"(d[1]), "+f"(d[2]), "+f"(d[3])
        : "r"(a[0]), "r"(a[1]), "r"(a[2]), "r"(a[3]), "r"(b[0]), "r"(b[1]));
}

__device__ __forceinline__ void cp_async16(uint32_t saddr, const void* g) {
    asm volatile("cp.async.cg.shared.global [%0], [%1], 16;"
                 :: "r"(saddr), "l"(g));
}
#define CP_COMMIT() asm volatile("cp.async.commit_group;" ::: "memory")
#define CP_WAIT0()  asm volatile("cp.async.wait_group 0;" ::: "memory")

// interleave position within an 8-group: pos(h) = ((h&3)<<1) | ((h&4)>>2)

// ---------------------------------------------------------------------------
// Prepass: fp32 -> tf32 bits, k-interleaved, for 7 matrices (row length 1024)
// ---------------------------------------------------------------------------
struct CvtArgs {
    const float4* src[7];
    uint32_t*     dst[7];
    int           n4[7];
};

__global__ __launch_bounds__(256) void cvt_kernel(CvtArgs a)
{
    const int z = blockIdx.y;
    const float4* s = a.src[z];
    uint32_t* d = a.dst[z];
    const int n4 = a.n4[z];
    const int stride = gridDim.x * blockDim.x;
    for (int i = blockIdx.x * blockDim.x + threadIdx.x; i < n4; i += stride) {
        float4 v = s[i];
        int e0   = i << 2;
        int col0 = e0 & 1023;
        int base = e0 - (col0 & 7) + ((col0 >> 2) & 1);
        d[base + 0] = f2tf32(v.x);
        d[base + 2] = f2tf32(v.y);
        d[base + 4] = f2tf32(v.z);
        d[base + 6] = f2tf32(v.w);
    }
}

// ---------------------------------------------------------------------------
// tf32 mma.sync GEMM. Operands pre-converted tf32, k-interleaved.
// CTA tile 128x128, K chunks of 32, 2-stage cp.async, GSTR=40.
// PERMUTE=true modes: z=0 Q (scale+ilv head-major), z=1 K (ilv head-major),
//                     z=2 V (TRANSPOSED [bh*64+hd][s], s-interleaved)
// ---------------------------------------------------------------------------
constexpr int GK     = 1024;
constexpr int KC     = 32;
constexpr int NCHUNK = GK / KC;
constexpr int GSTR   = 40;
constexpr int GTILE  = 128 * GSTR;
constexpr int GSTAGE = 2 * GTILE;
constexpr int GEMM_SMEM = 2 * GSTAGE * 4;   // 81920 bytes

struct GemmT {
    const uint32_t* A[3];
    const uint32_t* W[3];
    const float*    bias[3];
    void*           out[3];
};

template <bool PERMUTE>
__global__ __launch_bounds__(256, 2) void gemm_mma_kernel(GemmT args)
{
    const uint32_t* smu = (const uint32_t*)dyn_smem;
    const uint32_t smem_base = smem_u32(dyn_smem);

    const int z = blockIdx.z;
    const uint32_t* __restrict__ A = args.A[z];
    const uint32_t* __restrict__ W = args.W[z];
    const float* __restrict__ bias = args.bias[z];

    const int tid  = threadIdx.x;
    const int wid  = tid >> 5;
    const int lane = tid & 31;
    const int wm   = wid >> 2;
    const int wn   = wid & 3;
    const int bn   = blockIdx.x << 7;
    const int bm   = blockIdx.y << 7;
    const int lrow = lane >> 2;
    const int lcol = lane & 3;

    const uint32_t* Ab = A + (size_t)bm * GK;
    const uint32_t* Wb = W + (size_t)bn * GK;

    const int g_row = tid >> 3;
    const int g_c4  = (tid & 7) << 2;

    auto issue = [&](int c, int s) {
        const uint32_t base = smem_base + (uint32_t)s * GSTAGE * 4;
        const int kb = c * KC + g_c4;
#pragma unroll
        for (int t = 0; t < 4; ++t) {
            int row = g_row + t * 32;
            cp_async16(base + (uint32_t)(row * GSTR + g_c4) * 4,
                       Ab + (size_t)row * GK + kb);
            cp_async16(base + (uint32_t)(GTILE + row * GSTR + g_c4) * 4,
                       Wb + (size_t)row * GK + kb);
        }
        CP_COMMIT();
    };

    float acc[4][4][4];
#pragma unroll
    for (int i = 0; i < 4; ++i)
#pragma unroll
        for (int j = 0; j < 4; ++j)
#pragma unroll
            for (int r = 0; r < 4; ++r) acc[i][j][r] = 0.f;

    issue(0, 0);

    for (int c = 0; c < NCHUNK; ++c) {
        CP_WAIT0();
        __syncthreads();
        if (c + 1 < NCHUNK) issue(c + 1, (c + 1) & 1);

        const uint32_t* sa = smu + (c & 1) * GSTAGE;
        const uint32_t* sb = sa + GTILE;
#pragma unroll
        for (int ks = 0; ks < 4; ++ks) {
            const int k0 = ks * 8;
            uint32_t af[4][4], bf[4][2];
#pragma unroll
            for (int mi = 0; mi < 4; ++mi) {
                int r0 = wm * 64 + mi * 16 + lrow;
                const uint32_t* p = sa + r0 * GSTR + k0 + 2 * lcol;
                uint2 lo = *(const uint2*)p;
                uint2 hi = *(const uint2*)(p + 8 * GSTR);
                af[mi][0] = lo.x; af[mi][2] = lo.y;
                af[mi][1] = hi.x; af[mi][3] = hi.y;
            }
#pragma unroll
            for (int ni = 0; ni < 4; ++ni) {
                int n0 = wn * 32 + ni * 8 + lrow;
                uint2 b2 = *(const uint2*)(sb + n0 * GSTR + k0 + 2 * lcol);
                bf[ni][0] = b2.x; bf[ni][1] = b2.y;
            }
#pragma unroll
            for (int mi = 0; mi < 4; ++mi)
#pragma unroll
                for (int ni = 0; ni < 4; ++ni)
                    mma_tf32(acc[mi][ni], af[mi], bf[ni]);
        }
    }

    // epilogue
    if (PERMUTE) {
        uint32_t* out = (uint32_t*)args.out[z];
        const float scale = (z == 0) ? 0.125f : 1.f;
#pragma unroll
        for (int mi = 0; mi < 4; ++mi) {
            const int row0 = bm + wm * 64 + mi * 16 + lrow;
            const int row1 = row0 + 8;
#pragma unroll
            for (int ni = 0; ni < 4; ++ni) {
                const int col = bn + wn * 32 + ni * 8 + 2 * lcol;
                float2 bv = *(const float2*)&bias[col];
                float v00 = (acc[mi][ni][0] + bv.x) * scale;
                float v01 = (acc[mi][ni][1] + bv.y) * scale;
                float v10 = (acc[mi][ni][2] + bv.x) * scale;
                float v11 = (acc[mi][ni][3] + bv.y) * scale;
                const int h  = col >> 6;
                const int hd = col & 63;
                int b0 = row0 >> 11, s0 = row0 & 2047;
                int b1 = row1 >> 11, s1 = row1 & 2047;
                if (z != 2) {
                    size_t bi0 = ((size_t)(b0 * Hc + h) * Sc + s0) << 6;
                    size_t bi1 = ((size_t)(b1 * Hc + h) * Sc + s1) << 6;
                    int p0 = (hd & ~7) + (((hd & 3) << 1) | ((hd & 4) >> 2));
                    out[bi0 + p0]     = f2tf32(v00);
                    out[bi0 + p0 + 2] = f2tf32(v01);
                    out[bi1 + p0]     = f2tf32(v10);
                    out[bi1 + p0 + 2] = f2tf32(v11);
                } else {
                    // V^T: out[((b*H+h)*HD + hd) * Sc + s_ilv]
                    // s & 7 == lrow for all rows here
                    const int posr = ((lrow & 3) << 1) | (lrow >> 2);
                    size_t r0b = ((size_t)(b0 * Hc + h) * HDc + hd) * Sc
                                 + (s0 & ~7) + posr;
                    size_t r1b = ((size_t)(b1 * Hc + h) * HDc + hd) * Sc
                                 + (s1 & ~7) + posr;
                    out[r0b]      = f2tf32(v00);
                    out[r0b + Sc] = f2tf32(v01);
                    out[r1b]      = f2tf32(v10);
                    out[r1b + Sc] = f2tf32(v11);
                }
            }
        }
    } else {
        float* out = (float*)args.out[z];
#pragma unroll
        for (int mi = 0; mi < 4; ++mi) {
            const int row0 = bm + wm * 64 + mi * 16 + lrow;
            const int row1 = row0 + 8;
#pragma unroll
            for (int ni = 0; ni < 4; ++ni) {
                const int col = bn + wn * 32 + ni * 8 + 2 * lcol;
                float2 bv = *(const float2*)&bias[col];
                float2 o0 = { acc[mi][ni][0] + bv.x, acc[mi][ni][1] + bv.y };
                float2 o1 = { acc[mi][ni][2] + bv.x, acc[mi][ni][3] + bv.y };
                *(float2*)&out[(size_t)row0 * Dc + col] = o0;
                *(float2*)&out[(size_t)row1 * Dc + col] = o1;
            }
        }
    }
}

// ---------------------------------------------------------------------------
// Flash attention (causal), tf32 mma.sync, register-resident softmax.
// Q/K tf32 interleaved; V tf32 TRANSPOSED+interleaved -> PV b-frags = LDS.64.
// Warps 0-3 skip the fully-masked final half-tile.
// ---------------------------------------------------------------------------
constexpr int STR_Q = 72;
constexpr int STR_K = 72;
constexpr int STR_V = 72;
constexpr int OFF_Q = 0;
constexpr int OFF_K = OFF_Q + 128 * STR_Q;
constexpr int OFF_V = OFF_K + 2 * 64 * STR_K;
constexpr int ATTN_SMEM_U32 = OFF_V + 2 * 64 * STR_V;
constexpr int ATTN_SMEM_BYTES = ATTN_SMEM_U32 * 4;       // 110592

__global__ __launch_bounds__(256, 2) void attn_mma_kernel(
    const uint32_t* __restrict__ Q, const uint32_t* __restrict__ Kt,
    const uint32_t* __restrict__ V, uint32_t* __restrict__ ctx)
{
    uint32_t* smu = (uint32_t*)dyn_smem;
    const uint32_t smem_base = smem_u32(dyn_smem);

    const int tid  = threadIdx.x;
    const int wid  = tid >> 5;
    const int lane = tid & 31;
    const int lrow = lane >> 2;
    const int lcol = lane & 3;

    const int qt = gridDim.x - 1 - blockIdx.x;
    const int bh = blockIdx.y;

    // stage Q (tf32+interleaved+scaled already)
    const uint32_t* Qb = Q + ((size_t)bh * Sc + qt * 128) * HDc;
#pragma unroll
    for (int it = 0; it < 8; ++it) {
        int i  = tid + it * 256;
        int rr = i >> 4;
        int d4 = (i & 15) << 2;
        cp_async16(smem_base + (uint32_t)(OFF_Q + rr * STR_Q + d4) * 4,
                   Qb + rr * 64 + d4);
    }

    const uint32_t* VtB = V + (size_t)bh * HDc * Sc;   // V^T base

    auto issue_kv = [&](int kt, int bs) {
        const uint32_t* Kb = Kt + ((size_t)bh * Sc + kt * 64) * HDc;
#pragma unroll
        for (int it = 0; it < 4; ++it) {
            int i  = tid + it * 256;    // 0..1023
            int rr = i >> 4;            // 0..63 (seq row for K, hd row for Vt)
            int d4 = (i & 15) << 2;
            cp_async16(smem_base + (uint32_t)(OFF_K + bs * 64 * STR_K +
                                              rr * STR_K + d4) * 4,
                       Kb + rr * 64 + d4);
            cp_async16(smem_base + (uint32_t)(OFF_V + bs * 64 * STR_V +
                                              rr * STR_V + d4) * 4,
                       VtB + (size_t)rr * Sc + kt * 64 + d4);
        }
        CP_COMMIT();
    };

    const int nkt = 2 * qt + 2;
    issue_kv(0, 0);                      // commit covers Q stage too

    float m0 = -1e30f, m1 = -1e30f, l0 = 0.f, l1 = 0.f;
    float oacc[8][4];
#pragma unroll
    for (int ni = 0; ni < 8; ++ni)
#pragma unroll
        for (int t = 0; t < 4; ++t) oacc[ni][t] = 0.f;

    const int row_g0 = qt * 128 + wid * 16 + lrow;
    const int row_g1 = row_g0 + 8;
    const int s1lane = (lane & 28) | (lcol >> 1);
    const int s2lane = s1lane + 2;
    const bool par   = lcol & 1;
    const bool upper = (wid < 4);        // rows 0..63 of the q-tile

    for (int kt = 0; kt < nkt; ++kt) {
        const int bs = kt & 1;
        CP_WAIT0();
        __syncthreads();
        if (kt + 1 < nkt) issue_kv(kt + 1, bs ^ 1);

        // final half-tile is fully masked for warps 0-3: skip their compute
        if (upper && kt == 2 * qt + 1) continue;

        const uint32_t* sKr = smu + OFF_K + bs * 64 * STR_K;
        const uint32_t* sVr = smu + OFF_V + bs * 64 * STR_V;
        const uint32_t* sQu = smu + OFF_Q;

        // ---- S = Q @ K^T ----
        float sacc[8][4];
#pragma unroll
        for (int t = 0; t < 8; ++t)
#pragma unroll
            for (int j = 0; j < 4; ++j) sacc[t][j] = 0.f;

#pragma unroll
        for (int ks = 0; ks < 8; ++ks) {
            const int k0 = ks * 8;
            uint32_t af[4];
            {
                int r0 = wid * 16 + lrow;
                const uint32_t* p = sQu + r0 * STR_Q + k0 + 2 * lcol;
                uint2 lo = *(const uint2*)p;
                uint2 hi = *(const uint2*)(p + 8 * STR_Q);
                af[0] = lo.x; af[2] = lo.y;
                af[1] = hi.x; af[3] = hi.y;
            }
#pragma unroll
            for (int ni = 0; ni < 8; ++ni) {
                int n0 = ni * 8 + lrow;
                uint2 b2 = *(const uint2*)(sKr + n0 * STR_K + k0 + 2 * lcol);
                uint32_t bf[2] = { b2.x, b2.y };
                mma_tf32(sacc[ni], af, bf);
            }
        }

        // ---- causal mask ----
        if (kt >= 2 * qt) {
            const int cbase = kt * 64;
#pragma unroll
            for (int t = 0; t < 8; ++t) {
                int c0 = cbase + t * 8 + 2 * lcol;
                if (c0 > row_g0)     sacc[t][0] = -1e30f;
                if (c0 + 1 > row_g0) sacc[t][1] = -1e30f;
                if (c0 > row_g1)     sacc[t][2] = -1e30f;
                if (c0 + 1 > row_g1) sacc[t][3] = -1e30f;
            }
        }

        // ---- online softmax (registers) ----
        float mt0 = sacc[0][0], mt1 = sacc[0][2];
#pragma unroll
        for (int t = 0; t < 8; ++t) {
            mt0 = fmaxf(mt0, fmaxf(sacc[t][0], sacc[t][1]));
            mt1 = fmaxf(mt1, fmaxf(sacc[t][2], sacc[t][3]));
        }
        mt0 = fmaxf(mt0, __shfl_xor_sync(0xffffffffu, mt0, 1));
        mt0 = fmaxf(mt0, __shfl_xor_sync(0xffffffffu, mt0, 2));
        mt1 = fmaxf(mt1, __shfl_xor_sync(0xffffffffu, mt1, 1));
        mt1 = fmaxf(mt1, __shfl_xor_sync(0xffffffffu, mt1, 2));

        float mn0 = fmaxf(m0, mt0);
        float mn1 = fmaxf(m1, mt1);
        float c0f = __expf(m0 - mn0);
        float c1f = __expf(m1 - mn1);

        float ps0 = 0.f, ps1 = 0.f;
#pragma unroll
        for (int t = 0; t < 8; ++t) {
            sacc[t][0] = __expf(sacc[t][0] - mn0);
            sacc[t][1] = __expf(sacc[t][1] - mn0);
            sacc[t][2] = __expf(sacc[t][2] - mn1);
            sacc[t][3] = __expf(sacc[t][3] - mn1);
            ps0 += sacc[t][0] + sacc[t][1];
            ps1 += sacc[t][2] + sacc[t][3];
        }
        ps0 += __shfl_xor_sync(0xffffffffu, ps0, 1);
        ps0 += __shfl_xor_sync(0xffffffffu, ps0, 2);
        ps1 += __shfl_xor_sync(0xffffffffu, ps1, 1);
        ps1 += __shfl_xor_sync(0xffffffffu, ps1, 2);
        l0 = l0 * c0f + ps0;
        l1 = l1 * c1f + ps1;
        m0 = mn0; m1 = mn1;

#pragma unroll
        for (int ni = 0; ni < 8; ++ni) {
            oacc[ni][0] *= c0f; oacc[ni][1] *= c0f;
            oacc[ni][2] *= c1f; oacc[ni][3] *= c1f;
        }

        // ---- O += P @ V (P a-frags via quad shuffles; Vt b-frags LDS.64) ----
#pragma unroll
        for (int t = 0; t < 8; ++t) {
            float t00 = __shfl_sync(0xffffffffu, sacc[t][0], s1lane);
            float t01 = __shfl_sync(0xffffffffu, sacc[t][1], s1lane);
            float t10 = __shfl_sync(0xffffffffu, sacc[t][2], s1lane);
            float t11 = __shfl_sync(0xffffffffu, sacc[t][3], s1lane);
            float u00 = __shfl_sync(0xffffffffu, sacc[t][0], s2lane);
            float u01 = __shfl_sync(0xffffffffu, sacc[t][1], s2lane);
            float u10 = __shfl_sync(0xffffffffu, sacc[t][2], s2lane);
            float u11 = __shfl_sync(0xffffffffu, sacc[t][3], s2lane);
            uint32_t af[4];
            af[0] = f2tf32(par ? t01 : t00);
            af[1] = f2tf32(par ? t11 : t10);
            af[2] = f2tf32(par ? u01 : u00);
            af[3] = f2tf32(par ? u11 : u10);

            const int k0 = t * 8;
#pragma unroll
            for (int ni = 0; ni < 8; ++ni) {
                int n0 = ni * 8 + lrow;
                uint2 b2 = *(const uint2*)(sVr + n0 * STR_V + k0 + 2 * lcol);
                uint32_t bf[2] = { b2.x, b2.y };
                mma_tf32(oacc[ni], af, bf);
            }
        }
    }

    // ---- epilogue: normalize, store ctx as tf32 interleaved ----
    const float i0 = 1.f / l0;
    const float i1 = 1.f / l1;
    const int b_ = bh >> 4;
    const int h  = bh & 15;
    const int r0 = qt * 128 + wid * 16 + lrow;
    uint32_t* outU = ctx + ((size_t)(b_ * Sc) + r0) * Dc + h * HDc;
    const int e = 2 * lcol;
    const int pg = ((e & 3) << 1) | ((e & 4) >> 2);
#pragma unroll
    for (int ni = 0; ni < 8; ++ni) {
        int p0 = ni * 8 + pg;
        outU[p0]     = f2tf32(oacc[ni][0] * i0);
        outU[p0 + 2] = f2tf32(oacc[ni][1] * i0);
        outU[(size_t)8 * Dc + p0]     = f2tf32(oacc[ni][2] * i1);
        outU[(size_t)8 * Dc + p0 + 2] = f2tf32(oacc[ni][3] * i1);
    }
}

// ---------------------------------------------------------------------------
extern "C" void kernel_launch(void* const* d_in, const int* in_sizes, int n_in,
                              void* d_out, int out_size)
{
    const float* query = (const float*)d_in[0];
    const float* key   = (const float*)d_in[1];
    const float* value = (const float*)d_in[2];
    // d_in[3] = mask (causal tril) — applied analytically in attn kernel
    const float* Wq = (const float*)d_in[4];
    const float* bq = (const float*)d_in[5];
    const float* Wk = (const float*)d_in[6];
    const float* bk = (const float*)d_in[7];
    const float* Wv = (const float*)d_in[8];
    const float* bv = (const float*)d_in[9];
    const float* Wo = (const float*)d_in[10];
    const float* bo = (const float*)d_in[11];
    float* out = (float*)d_out;

    uint32_t *qp, *kp, *vp, *cp;
    uint32_t *qc, *kc, *vc, *wq, *wk, *wv, *wo;
    cudaGetSymbolAddress((void**)&qp, g_Q);
    cudaGetSymbolAddress((void**)&kp, g_K);
    cudaGetSymbolAddress((void**)&vp, g_V);
    cudaGetSymbolAddress((void**)&cp, g_ctx);
    cudaGetSymbolAddress((void**)&qc, g_qc);
    cudaGetSymbolAddress((void**)&kc, g_kc);
    cudaGetSymbolAddress((void**)&vc, g_vc);
    cudaGetSymbolAddress((void**)&wq, g_wq);
    cudaGetSymbolAddress((void**)&wk, g_wk);
    cudaGetSymbolAddress((void**)&wv, g_wv);
    cudaGetSymbolAddress((void**)&wo, g_wo);

    cudaFuncSetAttribute(gemm_mma_kernel<true>,
                         cudaFuncAttributeMaxDynamicSharedMemorySize, GEMM_SMEM);
    cudaFuncSetAttribute(gemm_mma_kernel<false>,
                         cudaFuncAttributeMaxDynamicSharedMemorySize, GEMM_SMEM);
    cudaFuncSetAttribute(attn_mma_kernel,
                         cudaFuncAttributeMaxDynamicSharedMemorySize,
                         ATTN_SMEM_BYTES);

    // prepass: convert + interleave inputs and weights
    CvtArgs ca;
    ca.src[0] = (const float4*)query; ca.dst[0] = qc; ca.n4[0] = Mc * Dc / 4;
    ca.src[1] = (const float4*)key;   ca.dst[1] = kc; ca.n4[1] = Mc * Dc / 4;
    ca.src[2] = (const float4*)value; ca.dst[2] = vc; ca.n4[2] = Mc * Dc / 4;
    ca.src[3] = (const float4*)Wq;    ca.dst[3] = wq; ca.n4[3] = Dc * Dc / 4;
    ca.src[4] = (const float4*)Wk;    ca.dst[4] = wk; ca.n4[4] = Dc * Dc / 4;
    ca.src[5] = (const float4*)Wv;    ca.dst[5] = wv; ca.n4[5] = Dc * Dc / 4;
    ca.src[6] = (const float4*)Wo;    ca.dst[6] = wo; ca.n4[6] = Dc * Dc / 4;
    cvt_kernel<<<dim3(512, 7), 256>>>(ca);

    // batched QKV projections
    GemmT qkv;
    qkv.A[0] = qc;  qkv.A[1] = kc;  qkv.A[2] = vc;
    qkv.W[0] = wq;  qkv.W[1] = wk;  qkv.W[2] = wv;
    qkv.bias[0] = bq; qkv.bias[1] = bk; qkv.bias[2] = bv;
    qkv.out[0] = qp;  qkv.out[1] = kp;  qkv.out[2] = vp;
    gemm_mma_kernel<true><<<dim3(Dc / 128, Mc / 128, 3), 256, GEMM_SMEM>>>(qkv);

    attn_mma_kernel<<<dim3(Sc / 128, Bc * Hc), 256, ATTN_SMEM_BYTES>>>(qp, kp, vp, cp);

    // O projection
    GemmT og;
    og.A[0] = cp; og.W[0] = wo; og.bias[0] = bo; og.out[0] = out;
    og.A[1] = og.A[2] = cp; og.W[1] = og.W[2] = wo;
    og.bias[1] = og.bias[2] = bo; og.out[1] = og.out[2] = out;
    gemm_mma_kernel<false><<<dim3(Dc / 128, Mc / 128, 1), 256, GEMM_SMEM>>>(og);
}